// round 2
// baseline (speedup 1.0000x reference)
#include <cuda_runtime.h>
#include <math.h>

#define BB 8
#define TT 96
#define EE 96
#define CC 256
#define HH 8
#define DD 32
#define HIDN 1024
#define NROWS (BB*TT*EE)   /* 73728 */
#define EPSI 1e-5f

// ---------------- scratch (static device globals; no allocations) ----------------
__device__ float g_X [NROWS*CC];   // running residual x
__device__ float g_XA[NROWS*CC];   // LN output (xs / xt / xm, reused)
__device__ float g_Q [NROWS*CC];
__device__ float g_K [NROWS*CC];
__device__ float g_V [NROWS*CC];
__device__ float g_O [NROWS*CC];
__device__ float g_P [NROWS*CC];
__device__ float g_Hd[NROWS*HIDN];

// ---------------- block reduce (256 threads) ----------------
__device__ __forceinline__ float blockReduce256(float v, float* red) {
    __syncthreads();  // protect red[] reuse across calls
    #pragma unroll
    for (int o = 16; o; o >>= 1) v += __shfl_xor_sync(0xffffffffu, v, o);
    int w = threadIdx.x >> 5, l = threadIdx.x & 31;
    if (!l) red[w] = v;
    __syncthreads();
    if (threadIdx.x < 32) {
        float t = (l < 8) ? red[l] : 0.f;
        #pragma unroll
        for (int o = 4; o; o >>= 1) t += __shfl_xor_sync(0xffffffffu, t, o);
        if (!l) red[8] = t;
    }
    __syncthreads();
    return red[8];
}

// ---------------- K1: X = x ; XA = LN(x; n1) ----------------
__global__ void k_ln1(const float* __restrict__ x,
                      const float* __restrict__ g, const float* __restrict__ b) {
    __shared__ float red[9];
    int r = blockIdx.x, c = threadIdx.x;
    int i = r * CC + c;
    float v = x[i];
    g_X[i] = v;
    float m = blockReduce256(v, red) * (1.f/CC);
    float d = v - m;
    float var = blockReduce256(d*d, red) * (1.f/CC);
    g_XA[i] = d * rsqrtf(var + EPSI) * g[c] + b[c];
}

// ---------------- SGEMM 128x128x8, 8x8 register tile ----------------
// EPI: 0 = plain, 1 = +bias, 2 = +bias then exact GELU, 3 = +bias +residual (in-place ok)
template<int EPI>
__global__ void __launch_bounds__(256)
sgemm_k(const float* __restrict__ A, const float* __restrict__ B,
        const float* __restrict__ bias, const float* __restrict__ Res,
        float* __restrict__ Cm, int M, int N, int K) {
    __shared__ float As[8][128];
    __shared__ float Bs[8][128];
    int tid = threadIdx.x;
    int bm = blockIdx.y * 128;
    int bn = blockIdx.x * 128;

    int aRow = tid >> 1;            // 0..127
    int aCol = (tid & 1) * 4;       // 0 or 4
    int bRow = tid >> 5;            // 0..7
    int bCol = (tid & 31) * 4;      // 0..124

    const float* Aptr = A + (bm + aRow) * K + aCol;
    const float* Bptr = B + bRow * N + bn + bCol;

    int ty = tid >> 4, tx = tid & 15;
    int m0 = ty * 8, n0 = tx * 8;

    float acc[8][8];
    #pragma unroll
    for (int i = 0; i < 8; i++)
        #pragma unroll
        for (int j = 0; j < 8; j++) acc[i][j] = 0.f;

    for (int k0 = 0; k0 < K; k0 += 8) {
        float4 av = *(const float4*)Aptr;
        float4 bv = *(const float4*)Bptr;
        As[aCol+0][aRow] = av.x; As[aCol+1][aRow] = av.y;
        As[aCol+2][aRow] = av.z; As[aCol+3][aRow] = av.w;
        *(float4*)&Bs[bRow][bCol] = bv;
        __syncthreads();
        #pragma unroll
        for (int kk = 0; kk < 8; kk++) {
            float4 a0 = *(const float4*)&As[kk][m0];
            float4 a1 = *(const float4*)&As[kk][m0+4];
            float4 b0 = *(const float4*)&Bs[kk][n0];
            float4 b1 = *(const float4*)&Bs[kk][n0+4];
            float a[8] = {a0.x,a0.y,a0.z,a0.w,a1.x,a1.y,a1.z,a1.w};
            float b[8] = {b0.x,b0.y,b0.z,b0.w,b1.x,b1.y,b1.z,b1.w};
            #pragma unroll
            for (int i = 0; i < 8; i++)
                #pragma unroll
                for (int j = 0; j < 8; j++)
                    acc[i][j] = fmaf(a[i], b[j], acc[i][j]);
        }
        __syncthreads();
        Aptr += 8;
        Bptr += 8 * N;
    }

    #pragma unroll
    for (int i = 0; i < 8; i++) {
        int m = bm + m0 + i;
        #pragma unroll
        for (int j = 0; j < 8; j++) {
            int n = bn + n0 + j;
            float v = acc[i][j];
            if (EPI >= 1) v += bias[n];
            if (EPI == 2) v = 0.5f * v * (1.f + erff(v * 0.70710678118654752f));
            if (EPI == 3) v += Res[m * N + n];
            Cm[m * N + n] = v;
        }
    }
}

// ---------------- attention (spatial masked-cosine / temporal softmax) ----------------
// grid: (B*T or B*E, H), 256 threads. Seq length 96, head dim 32.
#define ATTN_SMEM ((96*33*2 + 96*32 + 96*96) * 4)

template<bool TEMPORAL>
__global__ void attn_k(const float* __restrict__ Q, const float* __restrict__ Kb,
                       const float* __restrict__ V, float* __restrict__ O,
                       const float* __restrict__ adj) {
    extern __shared__ float sm[];
    float* sQ = sm;                 // [96][33]
    float* sK = sQ + 96*33;         // [96][33]
    float* sV = sK + 96*33;         // [96][32]
    float* sS = sV + 96*32;         // [96][96]
    int tid = threadIdx.x;
    int h = blockIdx.y;
    int base, stride;
    if (TEMPORAL) {
        int b = blockIdx.x / EE, e = blockIdx.x % EE;
        base = (b*TT*EE + e)*CC + h*DD;
        stride = EE*CC;
    } else {
        base = blockIdx.x * EE * CC + h*DD;
        stride = CC;
    }
    for (int i = tid; i < 96*32; i += 256) {
        int s = i >> 5, d = i & 31;
        int gi = base + s*stride + d;
        sQ[s*33+d] = Q[gi];
        sK[s*33+d] = Kb[gi];
        sV[s*32+d] = V[gi];
    }
    __syncthreads();
    for (int i = tid; i < 96*96; i += 256) {
        int qi = i / 96, ki = i % 96;
        float s = 0.f;
        #pragma unroll
        for (int d = 0; d < 32; d++) s = fmaf(sQ[qi*33+d], sK[ki*33+d], s);
        if (TEMPORAL) s *= 0.17677669529663687f;   // 1/sqrt(32)
        else          s = (s * adj[qi*96+ki] + 1.f) * 0.5f;
        sS[i] = s;
    }
    __syncthreads();
    if (TEMPORAL) {
        int w = tid >> 5, l = tid & 31;
        for (int r = w; r < 96; r += 8) {
            float v0 = sS[r*96+l], v1 = sS[r*96+32+l], v2 = sS[r*96+64+l];
            float mx = fmaxf(v0, fmaxf(v1, v2));
            #pragma unroll
            for (int o = 16; o; o >>= 1) mx = fmaxf(mx, __shfl_xor_sync(0xffffffffu, mx, o));
            float e0 = expf(v0-mx), e1 = expf(v1-mx), e2 = expf(v2-mx);
            float s = e0 + e1 + e2;
            #pragma unroll
            for (int o = 16; o; o >>= 1) s += __shfl_xor_sync(0xffffffffu, s, o);
            float inv = 1.f / s;
            sS[r*96+l] = e0*inv; sS[r*96+32+l] = e1*inv; sS[r*96+64+l] = e2*inv;
        }
        __syncthreads();
    }
    for (int i = tid; i < 96*32; i += 256) {
        int qi = i >> 5, d = i & 31;
        float o = 0.f;
        #pragma unroll 4
        for (int k = 0; k < 96; k++) o = fmaf(sS[qi*96+k], sV[k*32+d], o);
        O[base + qi*stride + d] = o;
    }
}

// ---------------- K5: p=LN(P;s_n); x += xs + s_gamma*p; XA = LN(x; n2) ----------------
__global__ void k_fuse1(const float* __restrict__ sng, const float* __restrict__ snb,
                        const float* __restrict__ sgam,
                        const float* __restrict__ n2g, const float* __restrict__ n2b) {
    __shared__ float red[9];
    int r = blockIdx.x, c = threadIdx.x;
    int i = r * CC + c;
    float p = g_P[i];
    float m1 = blockReduce256(p, red) * (1.f/CC);
    float d1 = p - m1;
    float v1 = blockReduce256(d1*d1, red) * (1.f/CC);
    float pn = d1 * rsqrtf(v1 + EPSI) * sng[c] + snb[c];
    float xn = g_X[i] + g_XA[i] + sgam[0] * pn;
    g_X[i] = xn;
    float m2 = blockReduce256(xn, red) * (1.f/CC);
    float d2 = xn - m2;
    float v2 = blockReduce256(d2*d2, red) * (1.f/CC);
    g_XA[i] = d2 * rsqrtf(v2 + EPSI) * n2g[c] + n2b[c];
}

// ---------------- K9: x += t_gamma*P; XA = LN(x; n3) ----------------
__global__ void k_fuse2(const float* __restrict__ tgam,
                        const float* __restrict__ n3g, const float* __restrict__ n3b) {
    __shared__ float red[9];
    int r = blockIdx.x, c = threadIdx.x;
    int i = r * CC + c;
    float xn = g_X[i] + tgam[0] * g_P[i];
    g_X[i] = xn;
    float m = blockReduce256(xn, red) * (1.f/CC);
    float d = xn - m;
    float v = blockReduce256(d*d, red) * (1.f/CC);
    g_XA[i] = d * rsqrtf(v + EPSI) * n3g[c] + n3b[c];
}

// ---------------- K12: temporal downsample (T=96 -> 48, w=0.5 exactly) ----------------
__global__ void k_down(float* __restrict__ out) {
    int i = blockIdx.x * blockDim.x + threadIdx.x;   // float4 index, total 2359296
    const float4* X4 = (const float4*)g_X;
    const int EC4 = EE*CC/4;                         // 6144
    int ec = i % EC4;
    int rest = i / EC4;
    int t2 = rest % 48;
    int b  = rest / 48;
    int in0 = (b*96 + 2*t2) * EC4 + ec;
    float4 a = X4[in0], c = X4[in0 + EC4];
    float4 o;
    o.x = 0.5f*(a.x + c.x); o.y = 0.5f*(a.y + c.y);
    o.z = 0.5f*(a.z + c.z); o.w = 0.5f*(a.w + c.w);
    ((float4*)out)[i] = o;
}

// ---------------- host ----------------
extern "C" void kernel_launch(void* const* d_in, const int* in_sizes, int n_in,
                              void* d_out, int out_size) {
    const float* x    = (const float*)d_in[0];
    const float* adj  = (const float*)d_in[1];
    const float* n1g  = (const float*)d_in[2];
    const float* n1b  = (const float*)d_in[3];
    const float* swq  = (const float*)d_in[4];
    const float* swk  = (const float*)d_in[5];
    const float* swv  = (const float*)d_in[6];
    const float* swp  = (const float*)d_in[7];
    const float* sbp  = (const float*)d_in[8];
    const float* sng  = (const float*)d_in[9];
    const float* snb  = (const float*)d_in[10];
    const float* sgam = (const float*)d_in[11];
    const float* n2g  = (const float*)d_in[12];
    const float* n2b  = (const float*)d_in[13];
    const float* twq  = (const float*)d_in[14];
    const float* twk  = (const float*)d_in[15];
    const float* twv  = (const float*)d_in[16];
    const float* twp  = (const float*)d_in[17];
    const float* tbp  = (const float*)d_in[18];
    const float* tgam = (const float*)d_in[19];
    const float* n3g  = (const float*)d_in[20];
    const float* n3b  = (const float*)d_in[21];
    const float* mw1  = (const float*)d_in[22];
    const float* mb1  = (const float*)d_in[23];
    const float* mw2  = (const float*)d_in[24];
    const float* mb2  = (const float*)d_in[25];

    float *X, *XA, *Q, *K, *V, *O, *P, *Hd;
    cudaGetSymbolAddress((void**)&X,  g_X);
    cudaGetSymbolAddress((void**)&XA, g_XA);
    cudaGetSymbolAddress((void**)&Q,  g_Q);
    cudaGetSymbolAddress((void**)&K,  g_K);
    cudaGetSymbolAddress((void**)&V,  g_V);
    cudaGetSymbolAddress((void**)&O,  g_O);
    cudaGetSymbolAddress((void**)&P,  g_P);
    cudaGetSymbolAddress((void**)&Hd, g_Hd);

    cudaFuncSetAttribute(attn_k<false>, cudaFuncAttributeMaxDynamicSharedMemorySize, ATTN_SMEM);
    cudaFuncSetAttribute(attn_k<true>,  cudaFuncAttributeMaxDynamicSharedMemorySize, ATTN_SMEM);

    dim3 g256(256/128, NROWS/128);    // (2, 576)
    dim3 g1024(1024/128, NROWS/128);  // (8, 576)

    // ---- spatial block ----
    k_ln1<<<NROWS, 256>>>(x, n1g, n1b);
    sgemm_k<0><<<g256, 256>>>(XA, swq, nullptr, nullptr, Q, NROWS, CC, CC);
    sgemm_k<0><<<g256, 256>>>(XA, swk, nullptr, nullptr, K, NROWS, CC, CC);
    sgemm_k<0><<<g256, 256>>>(XA, swv, nullptr, nullptr, V, NROWS, CC, CC);
    attn_k<false><<<dim3(BB*TT, HH), 256, ATTN_SMEM>>>(Q, K, V, O, adj);
    sgemm_k<1><<<g256, 256>>>(O, swp, sbp, nullptr, P, NROWS, CC, CC);
    k_fuse1<<<NROWS, 256>>>(sng, snb, sgam, n2g, n2b);

    // ---- temporal block ----
    sgemm_k<0><<<g256, 256>>>(XA, twq, nullptr, nullptr, Q, NROWS, CC, CC);
    sgemm_k<0><<<g256, 256>>>(XA, twk, nullptr, nullptr, K, NROWS, CC, CC);
    sgemm_k<0><<<g256, 256>>>(XA, twv, nullptr, nullptr, V, NROWS, CC, CC);
    attn_k<true><<<dim3(BB*EE, HH), 256, ATTN_SMEM>>>(Q, K, V, O, nullptr);
    sgemm_k<1><<<g256, 256>>>(O, twp, tbp, nullptr, P, NROWS, CC, CC);
    k_fuse2<<<NROWS, 256>>>(tgam, n3g, n3b);

    // ---- MLP ----
    sgemm_k<2><<<g1024, 256>>>(XA, mw1, mb1, nullptr, Hd, NROWS, HIDN, CC);
    sgemm_k<3><<<g256, 256>>>(Hd, mw2, mb2, X, X, NROWS, CC, HIDN);

    // ---- downsample ----
    k_down<<<(BB*48*EE*CC/4)/256, 256>>>((float*)d_out);

    (void)in_sizes; (void)n_in; (void)out_size;
}

// round 6
// speedup vs baseline: 2.0373x; 2.0373x over previous
#include <cuda_runtime.h>
#include <math.h>

#define BB 8
#define TT 96
#define EE 96
#define CC 256
#define HH 8
#define DD 32
#define HIDN 1024
#define NROWS (BB*TT*EE)   /* 73728 */
#define EPSI 1e-5f

// ---------------- scratch (static device globals; no allocations) ----------------
__device__ float g_X [NROWS*CC];   // running residual x
__device__ float g_XA[NROWS*CC];   // LN output (xs / xt / xm, reused)
__device__ float g_Q [NROWS*CC];
__device__ float g_K [NROWS*CC];
__device__ float g_V [NROWS*CC];
__device__ float g_O [NROWS*CC];
__device__ float g_P [NROWS*CC];
__device__ float g_Hd[NROWS*HIDN];

// ---------------- block reduce (256 threads) ----------------
__device__ __forceinline__ float blockReduce256(float v, float* red) {
    __syncthreads();  // protect red[] reuse across calls
    #pragma unroll
    for (int o = 16; o; o >>= 1) v += __shfl_xor_sync(0xffffffffu, v, o);
    int w = threadIdx.x >> 5, l = threadIdx.x & 31;
    if (!l) red[w] = v;
    __syncthreads();
    if (threadIdx.x < 32) {
        float t = (l < 8) ? red[l] : 0.f;
        #pragma unroll
        for (int o = 4; o; o >>= 1) t += __shfl_xor_sync(0xffffffffu, t, o);
        if (!l) red[8] = t;
    }
    __syncthreads();
    return red[8];
}

// ---------------- K1: X = x ; XA = LN(x; n1) ----------------
__global__ void k_ln1(const float* __restrict__ x,
                      const float* __restrict__ g, const float* __restrict__ b) {
    __shared__ float red[9];
    int r = blockIdx.x, c = threadIdx.x;
    int i = r * CC + c;
    float v = x[i];
    g_X[i] = v;
    float m = blockReduce256(v, red) * (1.f/CC);
    float d = v - m;
    float var = blockReduce256(d*d, red) * (1.f/CC);
    g_XA[i] = d * rsqrtf(var + EPSI) * g[c] + b[c];
}

// ---------------- bf16 pack helper ----------------
__device__ __forceinline__ unsigned packbf(float lo, float hi) {
    unsigned r;
    asm("cvt.rn.bf16x2.f32 %0, %1, %2;" : "=r"(r) : "f"(hi), "f"(lo));
    return r;
}

// ---------------- bf16 tensor-core GEMM 128x128x32, mma.m16n8k16 ----------------
// A [M,K] fp32 row-major, B [K,N] fp32 row-major, C fp32.
// EPI: 0 = plain, 1 = +bias, 2 = +bias then exact GELU, 3 = +bias +residual
#define A_STRIDE_U32 20   /* 40 bf16 per row (32 data + 8 pad) */
#define B_STRIDE_U16 132  /* 128 data + 4 pad */

template<int EPI>
__global__ void __launch_bounds__(256)
hgemm_k(const float* __restrict__ A, const float* __restrict__ B,
        const float* __restrict__ bias, const float* __restrict__ Res,
        float* __restrict__ Cm, int M, int N, int K) {
    __shared__ unsigned AsU[2][128 * A_STRIDE_U32];          // 20 KB
    __shared__ unsigned BsU[2][(32 * B_STRIDE_U16) / 2];     // 16.9 KB

    int tid  = threadIdx.x;
    int bm   = blockIdx.y * 128, bn = blockIdx.x * 128;
    int lane = tid & 31, warp = tid >> 5;
    int wm   = (warp & 1) * 64, wn = (warp >> 1) * 32;
    int g    = lane >> 2, tig = lane & 3;

    int rowA = tid >> 3, colA = (tid & 7) * 4;   // A tile: 128x32, 4 passes of 32 rows
    int rowB = tid >> 5, colB = (tid & 31) * 4;  // B tile: 32x128, 4 passes of 8 rows

    float acc[4][4][4];
    #pragma unroll
    for (int i = 0; i < 4; i++)
        #pragma unroll
        for (int j = 0; j < 4; j++)
            #pragma unroll
            for (int k = 0; k < 4; k++) acc[i][j][k] = 0.f;

    float4 pa[4], pb[4];

    int kTiles = K >> 5;

    // prefetch tile 0
    #pragma unroll
    for (int p = 0; p < 4; p++)
        pa[p] = *(const float4*)&A[(bm + rowA + p*32) * K + colA];
    #pragma unroll
    for (int p = 0; p < 4; p++)
        pb[p] = *(const float4*)&B[(rowB + p*8) * N + bn + colB];
    #pragma unroll
    for (int p = 0; p < 4; p++) {
        unsigned* d = &AsU[0][(rowA + p*32) * A_STRIDE_U32 + (colA >> 1)];
        d[0] = packbf(pa[p].x, pa[p].y);
        d[1] = packbf(pa[p].z, pa[p].w);
    }
    #pragma unroll
    for (int p = 0; p < 4; p++) {
        unsigned* d = &BsU[0][((rowB + p*8) * B_STRIDE_U16 + colB) >> 1];
        d[0] = packbf(pb[p].x, pb[p].y);
        d[1] = packbf(pb[p].z, pb[p].w);
    }
    __syncthreads();

    for (int kt = 0; kt < kTiles; ++kt) {
        int buf = kt & 1;
        bool hasNext = (kt + 1 < kTiles);
        if (hasNext) {
            int kOff = (kt + 1) * 32;
            #pragma unroll
            for (int p = 0; p < 4; p++)
                pa[p] = *(const float4*)&A[(bm + rowA + p*32) * K + kOff + colA];
            #pragma unroll
            for (int p = 0; p < 4; p++)
                pb[p] = *(const float4*)&B[(kOff + rowB + p*8) * N + bn + colB];
        }

        #pragma unroll
        for (int kh = 0; kh < 2; ++kh) {
            unsigned af[4][4];
            unsigned bfr[4][2];
            #pragma unroll
            for (int mi = 0; mi < 4; ++mi) {
                const unsigned* p = &AsU[buf][(wm + mi*16 + g) * A_STRIDE_U32 + kh*8 + tig];
                af[mi][0] = p[0];
                af[mi][1] = p[8 * A_STRIDE_U32];
                af[mi][2] = p[4];
                af[mi][3] = p[8 * A_STRIDE_U32 + 4];
            }
            const unsigned short* Bs16 = (const unsigned short*)BsU[buf];
            #pragma unroll
            for (int ni = 0; ni < 4; ++ni) {
                int ccol = wn + ni*8 + g;
                int k0 = kh*16 + tig*2;
                unsigned lo0 = Bs16[ k0      * B_STRIDE_U16 + ccol];
                unsigned hi0 = Bs16[(k0 + 1) * B_STRIDE_U16 + ccol];
                unsigned lo1 = Bs16[(k0 + 8) * B_STRIDE_U16 + ccol];
                unsigned hi1 = Bs16[(k0 + 9) * B_STRIDE_U16 + ccol];
                bfr[ni][0] = lo0 | (hi0 << 16);
                bfr[ni][1] = lo1 | (hi1 << 16);
            }
            #pragma unroll
            for (int mi = 0; mi < 4; ++mi)
                #pragma unroll
                for (int ni = 0; ni < 4; ++ni)
                    asm volatile(
                        "mma.sync.aligned.m16n8k16.row.col.f32.bf16.bf16.f32 "
                        "{%0,%1,%2,%3},{%4,%5,%6,%7},{%8,%9},{%0,%1,%2,%3};"
                        : "+f"(acc[mi][ni][0]), "+f"(acc[mi][ni][1]),
                          "+f"(acc[mi][ni][2]), "+f"(acc[mi][ni][3])
                        : "r"(af[mi][0]), "r"(af[mi][1]), "r"(af[mi][2]), "r"(af[mi][3]),
                          "r"(bfr[ni][0]), "r"(bfr[ni][1]));
        }

        if (hasNext) {
            int nb = buf ^ 1;
            #pragma unroll
            for (int p = 0; p < 4; p++) {
                unsigned* d = &AsU[nb][(rowA + p*32) * A_STRIDE_U32 + (colA >> 1)];
                d[0] = packbf(pa[p].x, pa[p].y);
                d[1] = packbf(pa[p].z, pa[p].w);
            }
            #pragma unroll
            for (int p = 0; p < 4; p++) {
                unsigned* d = &BsU[nb][((rowB + p*8) * B_STRIDE_U16 + colB) >> 1];
                d[0] = packbf(pb[p].x, pb[p].y);
                d[1] = packbf(pb[p].z, pb[p].w);
            }
            __syncthreads();
        }
    }

    // epilogue
    #pragma unroll
    for (int mi = 0; mi < 4; ++mi) {
        int r0 = bm + wm + mi*16 + g;
        #pragma unroll
        for (int ni = 0; ni < 4; ++ni) {
            int c = bn + wn + ni*8 + tig*2;
            float v0 = acc[mi][ni][0], v1 = acc[mi][ni][1];
            float v2 = acc[mi][ni][2], v3 = acc[mi][ni][3];
            if (EPI >= 1) {
                float b0 = bias[c], b1 = bias[c+1];
                v0 += b0; v1 += b1; v2 += b0; v3 += b1;
            }
            if (EPI == 2) {
                v0 = 0.5f * v0 * (1.f + erff(v0 * 0.70710678118654752f));
                v1 = 0.5f * v1 * (1.f + erff(v1 * 0.70710678118654752f));
                v2 = 0.5f * v2 * (1.f + erff(v2 * 0.70710678118654752f));
                v3 = 0.5f * v3 * (1.f + erff(v3 * 0.70710678118654752f));
            }
            if (EPI == 3) {
                float2 ra = *(const float2*)&Res[r0 * N + c];
                float2 rb = *(const float2*)&Res[(r0 + 8) * N + c];
                v0 += ra.x; v1 += ra.y; v2 += rb.x; v3 += rb.y;
            }
            float2 o0; o0.x = v0; o0.y = v1;
            float2 o1; o1.x = v2; o1.y = v3;
            *(float2*)&Cm[r0 * N + c]       = o0;
            *(float2*)&Cm[(r0 + 8) * N + c] = o1;
        }
    }
}

// ---------------- attention (spatial masked-cosine / temporal softmax) ----------------
// grid: (B*T or B*E, H), 256 threads. Seq length 96, head dim 32.
#define ATTN_SMEM ((96*33*2 + 96*32 + 96*96) * 4)

template<bool TEMPORAL>
__global__ void attn_k(const float* __restrict__ Q, const float* __restrict__ Kb,
                       const float* __restrict__ V, float* __restrict__ O,
                       const float* __restrict__ adj) {
    extern __shared__ float sm[];
    float* sQ = sm;                 // [96][33]
    float* sK = sQ + 96*33;         // [96][33]
    float* sV = sK + 96*33;         // [96][32]
    float* sS = sV + 96*32;         // [96][96]
    int tid = threadIdx.x;
    int h = blockIdx.y;
    int base, stride;
    if (TEMPORAL) {
        int b = blockIdx.x / EE, e = blockIdx.x % EE;
        base = (b*TT*EE + e)*CC + h*DD;
        stride = EE*CC;
    } else {
        base = blockIdx.x * EE * CC + h*DD;
        stride = CC;
    }
    for (int i = tid; i < 96*32; i += 256) {
        int s = i >> 5, d = i & 31;
        int gi = base + s*stride + d;
        sQ[s*33+d] = Q[gi];
        sK[s*33+d] = Kb[gi];
        sV[s*32+d] = V[gi];
    }
    __syncthreads();
    for (int i = tid; i < 96*96; i += 256) {
        int qi = i / 96, ki = i % 96;
        float s = 0.f;
        #pragma unroll
        for (int d = 0; d < 32; d++) s = fmaf(sQ[qi*33+d], sK[ki*33+d], s);
        if (TEMPORAL) s *= 0.17677669529663687f;   // 1/sqrt(32)
        else          s = (s * adj[qi*96+ki] + 1.f) * 0.5f;
        sS[i] = s;
    }
    __syncthreads();
    if (TEMPORAL) {
        int w = tid >> 5, l = tid & 31;
        for (int r = w; r < 96; r += 8) {
            float v0 = sS[r*96+l], v1 = sS[r*96+32+l], v2 = sS[r*96+64+l];
            float mx = fmaxf(v0, fmaxf(v1, v2));
            #pragma unroll
            for (int o = 16; o; o >>= 1) mx = fmaxf(mx, __shfl_xor_sync(0xffffffffu, mx, o));
            float e0 = expf(v0-mx), e1 = expf(v1-mx), e2 = expf(v2-mx);
            float s = e0 + e1 + e2;
            #pragma unroll
            for (int o = 16; o; o >>= 1) s += __shfl_xor_sync(0xffffffffu, s, o);
            float inv = 1.f / s;
            sS[r*96+l] = e0*inv; sS[r*96+32+l] = e1*inv; sS[r*96+64+l] = e2*inv;
        }
        __syncthreads();
    }
    for (int i = tid; i < 96*32; i += 256) {
        int qi = i >> 5, d = i & 31;
        float o = 0.f;
        #pragma unroll 4
        for (int k = 0; k < 96; k++) o = fmaf(sS[qi*96+k], sV[k*32+d], o);
        O[base + qi*stride + d] = o;
    }
}

// ---------------- K5: p=LN(P;s_n); x += xs + s_gamma*p; XA = LN(x; n2) ----------------
__global__ void k_fuse1(const float* __restrict__ sng, const float* __restrict__ snb,
                        const float* __restrict__ sgam,
                        const float* __restrict__ n2g, const float* __restrict__ n2b) {
    __shared__ float red[9];
    int r = blockIdx.x, c = threadIdx.x;
    int i = r * CC + c;
    float p = g_P[i];
    float m1 = blockReduce256(p, red) * (1.f/CC);
    float d1 = p - m1;
    float v1 = blockReduce256(d1*d1, red) * (1.f/CC);
    float pn = d1 * rsqrtf(v1 + EPSI) * sng[c] + snb[c];
    float xn = g_X[i] + g_XA[i] + sgam[0] * pn;
    g_X[i] = xn;
    float m2 = blockReduce256(xn, red) * (1.f/CC);
    float d2 = xn - m2;
    float v2 = blockReduce256(d2*d2, red) * (1.f/CC);
    g_XA[i] = d2 * rsqrtf(v2 + EPSI) * n2g[c] + n2b[c];
}

// ---------------- K9: x += t_gamma*P; XA = LN(x; n3) ----------------
__global__ void k_fuse2(const float* __restrict__ tgam,
                        const float* __restrict__ n3g, const float* __restrict__ n3b) {
    __shared__ float red[9];
    int r = blockIdx.x, c = threadIdx.x;
    int i = r * CC + c;
    float xn = g_X[i] + tgam[0] * g_P[i];
    g_X[i] = xn;
    float m = blockReduce256(xn, red) * (1.f/CC);
    float d = xn - m;
    float v = blockReduce256(d*d, red) * (1.f/CC);
    g_XA[i] = d * rsqrtf(v + EPSI) * n3g[c] + n3b[c];
}

// ---------------- K12: temporal downsample (T=96 -> 48, w=0.5 exactly) ----------------
__global__ void k_down(float* __restrict__ out) {
    int i = blockIdx.x * blockDim.x + threadIdx.x;   // float4 index
    const float4* X4 = (const float4*)g_X;
    const int EC4 = EE*CC/4;                         // 6144
    int ec = i % EC4;
    int rest = i / EC4;
    int t2 = rest % 48;
    int b  = rest / 48;
    int in0 = (b*96 + 2*t2) * EC4 + ec;
    float4 a = X4[in0], c = X4[in0 + EC4];
    float4 o;
    o.x = 0.5f*(a.x + c.x); o.y = 0.5f*(a.y + c.y);
    o.z = 0.5f*(a.z + c.z); o.w = 0.5f*(a.w + c.w);
    ((float4*)out)[i] = o;
}

// ---------------- host ----------------
extern "C" void kernel_launch(void* const* d_in, const int* in_sizes, int n_in,
                              void* d_out, int out_size) {
    const float* x    = (const float*)d_in[0];
    const float* adj  = (const float*)d_in[1];
    const float* n1g  = (const float*)d_in[2];
    const float* n1b  = (const float*)d_in[3];
    const float* swq  = (const float*)d_in[4];
    const float* swk  = (const float*)d_in[5];
    const float* swv  = (const float*)d_in[6];
    const float* swp  = (const float*)d_in[7];
    const float* sbp  = (const float*)d_in[8];
    const float* sng  = (const float*)d_in[9];
    const float* snb  = (const float*)d_in[10];
    const float* sgam = (const float*)d_in[11];
    const float* n2g  = (const float*)d_in[12];
    const float* n2b  = (const float*)d_in[13];
    const float* twq  = (const float*)d_in[14];
    const float* twk  = (const float*)d_in[15];
    const float* twv  = (const float*)d_in[16];
    const float* twp  = (const float*)d_in[17];
    const float* tbp  = (const float*)d_in[18];
    const float* tgam = (const float*)d_in[19];
    const float* n3g  = (const float*)d_in[20];
    const float* n3b  = (const float*)d_in[21];
    const float* mw1  = (const float*)d_in[22];
    const float* mb1  = (const float*)d_in[23];
    const float* mw2  = (const float*)d_in[24];
    const float* mb2  = (const float*)d_in[25];

    float *X, *XA, *Q, *K, *V, *O, *P, *Hd;
    cudaGetSymbolAddress((void**)&X,  g_X);
    cudaGetSymbolAddress((void**)&XA, g_XA);
    cudaGetSymbolAddress((void**)&Q,  g_Q);
    cudaGetSymbolAddress((void**)&K,  g_K);
    cudaGetSymbolAddress((void**)&V,  g_V);
    cudaGetSymbolAddress((void**)&O,  g_O);
    cudaGetSymbolAddress((void**)&P,  g_P);
    cudaGetSymbolAddress((void**)&Hd, g_Hd);

    cudaFuncSetAttribute(attn_k<false>, cudaFuncAttributeMaxDynamicSharedMemorySize, ATTN_SMEM);
    cudaFuncSetAttribute(attn_k<true>,  cudaFuncAttributeMaxDynamicSharedMemorySize, ATTN_SMEM);

    dim3 g256(256/128, NROWS/128);    // (2, 576)
    dim3 g1024(1024/128, NROWS/128);  // (8, 576)

    // ---- spatial block ----
    k_ln1<<<NROWS, 256>>>(x, n1g, n1b);
    hgemm_k<0><<<g256, 256>>>(XA, swq, nullptr, nullptr, Q, NROWS, CC, CC);
    hgemm_k<0><<<g256, 256>>>(XA, swk, nullptr, nullptr, K, NROWS, CC, CC);
    hgemm_k<0><<<g256, 256>>>(XA, swv, nullptr, nullptr, V, NROWS, CC, CC);
    attn_k<false><<<dim3(BB*TT, HH), 256, ATTN_SMEM>>>(Q, K, V, O, adj);
    hgemm_k<1><<<g256, 256>>>(O, swp, sbp, nullptr, P, NROWS, CC, CC);
    k_fuse1<<<NROWS, 256>>>(sng, snb, sgam, n2g, n2b);

    // ---- temporal block ----
    hgemm_k<0><<<g256, 256>>>(XA, twq, nullptr, nullptr, Q, NROWS, CC, CC);
    hgemm_k<0><<<g256, 256>>>(XA, twk, nullptr, nullptr, K, NROWS, CC, CC);
    hgemm_k<0><<<g256, 256>>>(XA, twv, nullptr, nullptr, V, NROWS, CC, CC);
    attn_k<true><<<dim3(BB*EE, HH), 256, ATTN_SMEM>>>(Q, K, V, O, nullptr);
    hgemm_k<1><<<g256, 256>>>(O, twp, tbp, nullptr, P, NROWS, CC, CC);
    k_fuse2<<<NROWS, 256>>>(tgam, n3g, n3b);

    // ---- MLP ----
    hgemm_k<2><<<g1024, 256>>>(XA, mw1, mb1, nullptr, Hd, NROWS, HIDN, CC);
    hgemm_k<3><<<g256, 256>>>(Hd, mw2, mb2, X, X, NROWS, CC, HIDN);

    // ---- downsample ----
    k_down<<<(BB*48*EE*CC/4)/256, 256>>>((float*)d_out);

    (void)in_sizes; (void)n_in; (void)out_size;
}

// round 7
// speedup vs baseline: 3.0449x; 1.4946x over previous
#include <cuda_runtime.h>
#include <math.h>

#define BB 8
#define TT 96
#define EE 96
#define CC 256
#define HH 8
#define DD 32
#define HIDN 1024
#define NROWS (BB*TT*EE)   /* 73728 */
#define EPSI 1e-5f

// ---------------- scratch (static device globals; no allocations) ----------------
__device__ float g_X [NROWS*CC];   // running residual x
__device__ float g_XA[NROWS*CC];   // LN output (xs / xt / xm, reused)
__device__ float g_Q [NROWS*CC];
__device__ float g_K [NROWS*CC];
__device__ float g_V [NROWS*CC];
__device__ float g_O [NROWS*CC];
__device__ float g_P [NROWS*CC];
__device__ float g_Hd[NROWS*HIDN];

__device__ __forceinline__ float warpSum(float v) {
    #pragma unroll
    for (int o = 16; o; o >>= 1) v += __shfl_xor_sync(0xffffffffu, v, o);
    return v;
}

// ---------------- bf16 pack helper (lo in bits 0-15, hi in bits 16-31) -----------
__device__ __forceinline__ unsigned packbf(float lo, float hi) {
    unsigned r;
    asm("cvt.rn.bf16x2.f32 %0, %1, %2;" : "=r"(r) : "f"(hi), "f"(lo));
    return r;
}

#define MMA16816(c0,c1,c2,c3,a0,a1,a2,a3,b0,b1) \
    asm volatile( \
        "mma.sync.aligned.m16n8k16.row.col.f32.bf16.bf16.f32 " \
        "{%0,%1,%2,%3},{%4,%5,%6,%7},{%8,%9},{%0,%1,%2,%3};" \
        : "+f"(c0), "+f"(c1), "+f"(c2), "+f"(c3) \
        : "r"(a0), "r"(a1), "r"(a2), "r"(a3), "r"(b0), "r"(b1))

// ---------------- K1: X = x ; XA = LN(x; n1)  (warp-per-row) ----------------
__global__ void k_ln1(const float* __restrict__ x,
                      const float* __restrict__ g, const float* __restrict__ b) {
    int warp = threadIdx.x >> 5, lane = threadIdx.x & 31;
    int row = blockIdx.x * 8 + warp;
    const float4* xr = (const float4*)(x + row*CC);
    float4 a0 = xr[lane], a1 = xr[lane+32];
    float4* Xr = (float4*)(g_X + row*CC);
    Xr[lane] = a0; Xr[lane+32] = a1;
    float f[8] = {a0.x,a0.y,a0.z,a0.w,a1.x,a1.y,a1.z,a1.w};
    float s = 0.f;
    #pragma unroll
    for (int j = 0; j < 8; j++) s += f[j];
    float m = warpSum(s) * (1.f/CC);
    float vs = 0.f;
    #pragma unroll
    for (int j = 0; j < 8; j++) { f[j] -= m; vs += f[j]*f[j]; }
    float r = rsqrtf(warpSum(vs) * (1.f/CC) + EPSI);
    float4 ga = ((const float4*)g)[lane], gb = ((const float4*)g)[lane+32];
    float4 ba = ((const float4*)b)[lane], bb = ((const float4*)b)[lane+32];
    float gf[8] = {ga.x,ga.y,ga.z,ga.w,gb.x,gb.y,gb.z,gb.w};
    float bf_[8] = {ba.x,ba.y,ba.z,ba.w,bb.x,bb.y,bb.z,bb.w};
    float o[8];
    #pragma unroll
    for (int j = 0; j < 8; j++) o[j] = f[j]*r*gf[j] + bf_[j];
    float4* Or = (float4*)(g_XA + row*CC);
    float4 o0 = {o[0],o[1],o[2],o[3]}, o1 = {o[4],o[5],o[6],o[7]};
    Or[lane] = o0; Or[lane+32] = o1;
}

// ---------------- bf16 tensor-core GEMM 128x128x32, mma.m16n8k16 ----------------
#define A_STRIDE_U32 20   /* 40 bf16 per row (32 data + 8 pad) */
#define B_STRIDE_U16 132  /* 128 data + 4 pad */

template<int EPI>
__global__ void __launch_bounds__(256)
hgemm_k(const float* __restrict__ A, const float* __restrict__ B,
        const float* __restrict__ bias, const float* __restrict__ Res,
        float* __restrict__ Cm, int M, int N, int K) {
    __shared__ unsigned AsU[2][128 * A_STRIDE_U32];
    __shared__ unsigned BsU[2][(32 * B_STRIDE_U16) / 2];

    int tid  = threadIdx.x;
    int bm   = blockIdx.y * 128, bn = blockIdx.x * 128;
    int lane = tid & 31, warp = tid >> 5;
    int wm   = (warp & 1) * 64, wn = (warp >> 1) * 32;
    int g    = lane >> 2, tig = lane & 3;

    int rowA = tid >> 3, colA = (tid & 7) * 4;
    int rowB = tid >> 5, colB = (tid & 31) * 4;

    float acc[4][4][4];
    #pragma unroll
    for (int i = 0; i < 4; i++)
        #pragma unroll
        for (int j = 0; j < 4; j++)
            #pragma unroll
            for (int k = 0; k < 4; k++) acc[i][j][k] = 0.f;

    float4 pa[4], pb[4];
    int kTiles = K >> 5;

    #pragma unroll
    for (int p = 0; p < 4; p++)
        pa[p] = *(const float4*)&A[(bm + rowA + p*32) * K + colA];
    #pragma unroll
    for (int p = 0; p < 4; p++)
        pb[p] = *(const float4*)&B[(rowB + p*8) * N + bn + colB];
    #pragma unroll
    for (int p = 0; p < 4; p++) {
        unsigned* d = &AsU[0][(rowA + p*32) * A_STRIDE_U32 + (colA >> 1)];
        d[0] = packbf(pa[p].x, pa[p].y);
        d[1] = packbf(pa[p].z, pa[p].w);
    }
    #pragma unroll
    for (int p = 0; p < 4; p++) {
        unsigned* d = &BsU[0][((rowB + p*8) * B_STRIDE_U16 + colB) >> 1];
        d[0] = packbf(pb[p].x, pb[p].y);
        d[1] = packbf(pb[p].z, pb[p].w);
    }
    __syncthreads();

    for (int kt = 0; kt < kTiles; ++kt) {
        int buf = kt & 1;
        bool hasNext = (kt + 1 < kTiles);
        if (hasNext) {
            int kOff = (kt + 1) * 32;
            #pragma unroll
            for (int p = 0; p < 4; p++)
                pa[p] = *(const float4*)&A[(bm + rowA + p*32) * K + kOff + colA];
            #pragma unroll
            for (int p = 0; p < 4; p++)
                pb[p] = *(const float4*)&B[(kOff + rowB + p*8) * N + bn + colB];
        }

        #pragma unroll
        for (int kh = 0; kh < 2; ++kh) {
            unsigned af[4][4];
            unsigned bfr[4][2];
            #pragma unroll
            for (int mi = 0; mi < 4; ++mi) {
                const unsigned* p = &AsU[buf][(wm + mi*16 + g) * A_STRIDE_U32 + kh*8 + tig];
                af[mi][0] = p[0];
                af[mi][1] = p[8 * A_STRIDE_U32];
                af[mi][2] = p[4];
                af[mi][3] = p[8 * A_STRIDE_U32 + 4];
            }
            const unsigned short* Bs16 = (const unsigned short*)BsU[buf];
            #pragma unroll
            for (int ni = 0; ni < 4; ++ni) {
                int ccol = wn + ni*8 + g;
                int k0 = kh*16 + tig*2;
                unsigned lo0 = Bs16[ k0      * B_STRIDE_U16 + ccol];
                unsigned hi0 = Bs16[(k0 + 1) * B_STRIDE_U16 + ccol];
                unsigned lo1 = Bs16[(k0 + 8) * B_STRIDE_U16 + ccol];
                unsigned hi1 = Bs16[(k0 + 9) * B_STRIDE_U16 + ccol];
                bfr[ni][0] = lo0 | (hi0 << 16);
                bfr[ni][1] = lo1 | (hi1 << 16);
            }
            #pragma unroll
            for (int mi = 0; mi < 4; ++mi)
                #pragma unroll
                for (int ni = 0; ni < 4; ++ni)
                    MMA16816(acc[mi][ni][0], acc[mi][ni][1], acc[mi][ni][2], acc[mi][ni][3],
                             af[mi][0], af[mi][1], af[mi][2], af[mi][3],
                             bfr[ni][0], bfr[ni][1]);
        }

        if (hasNext) {
            int nb = buf ^ 1;
            #pragma unroll
            for (int p = 0; p < 4; p++) {
                unsigned* d = &AsU[nb][(rowA + p*32) * A_STRIDE_U32 + (colA >> 1)];
                d[0] = packbf(pa[p].x, pa[p].y);
                d[1] = packbf(pa[p].z, pa[p].w);
            }
            #pragma unroll
            for (int p = 0; p < 4; p++) {
                unsigned* d = &BsU[nb][((rowB + p*8) * B_STRIDE_U16 + colB) >> 1];
                d[0] = packbf(pb[p].x, pb[p].y);
                d[1] = packbf(pb[p].z, pb[p].w);
            }
            __syncthreads();
        }
    }

    #pragma unroll
    for (int mi = 0; mi < 4; ++mi) {
        int r0 = bm + wm + mi*16 + g;
        #pragma unroll
        for (int ni = 0; ni < 4; ++ni) {
            int c = bn + wn + ni*8 + tig*2;
            float v0 = acc[mi][ni][0], v1 = acc[mi][ni][1];
            float v2 = acc[mi][ni][2], v3 = acc[mi][ni][3];
            if (EPI >= 1) {
                float b0 = bias[c], b1 = bias[c+1];
                v0 += b0; v1 += b1; v2 += b0; v3 += b1;
            }
            if (EPI == 2) {
                v0 = 0.5f * v0 * (1.f + erff(v0 * 0.70710678118654752f));
                v1 = 0.5f * v1 * (1.f + erff(v1 * 0.70710678118654752f));
                v2 = 0.5f * v2 * (1.f + erff(v2 * 0.70710678118654752f));
                v3 = 0.5f * v3 * (1.f + erff(v3 * 0.70710678118654752f));
            }
            if (EPI == 3) {
                float2 ra = *(const float2*)&Res[r0 * N + c];
                float2 rb = *(const float2*)&Res[(r0 + 8) * N + c];
                v0 += ra.x; v1 += ra.y; v2 += rb.x; v3 += rb.y;
            }
            float2 o0; o0.x = v0; o0.y = v1;
            float2 o1; o1.x = v2; o1.y = v3;
            *(float2*)&Cm[r0 * N + c]       = o0;
            *(float2*)&Cm[(r0 + 8) * N + c] = o1;
        }
    }
}

// ---------------- attention via bf16 mma ----------------
// smem layout (u32 units):
#define O_SQ   0                  /* 96 x 20 u32 (stride 40 bf16) */
#define O_SK   1920
#define O_SVT  3840               /* 32 x 49 u32 (stride 98 bf16, V transposed) */
#define O_SS   5408               /* 96 x 52 u32 (stride 104 bf16) */
#define O_PART 10400              /* 8 x 32 fp32 partial colsums */
#define O_COL  10656              /* 32 fp32 colsums */
#define O_SF   10688              /* 96 x 97 fp32 (adj or softmax scratch) */
#define ATTN_U32 (O_SF + 96*97)
#define ATTN_SMEM (ATTN_U32 * 4)  /* 80000 bytes */

template<bool TEMPORAL>
__global__ void __launch_bounds__(256)
attn_mma(const float* __restrict__ Q, const float* __restrict__ Kb,
         const float* __restrict__ V, float* __restrict__ O,
         const float* __restrict__ adj) {
    extern __shared__ unsigned su[];
    unsigned* sQ  = su + O_SQ;
    unsigned* sK  = su + O_SK;
    unsigned* sVt = su + O_SVT;
    unsigned* sS  = su + O_SS;
    float* sPart  = (float*)(su + O_PART);
    float* sCol   = (float*)(su + O_COL);
    float* sF     = (float*)(su + O_SF);

    int tid = threadIdx.x, lane = tid & 31, warp = tid >> 5;
    int g = lane >> 2, tig = lane & 3;
    int h = blockIdx.y;
    int base, stride;
    if (TEMPORAL) {
        int b = blockIdx.x / EE, e = blockIdx.x % EE;
        base = (b*TT*EE + e)*CC + h*DD;
        stride = EE*CC;
    } else {
        base = blockIdx.x * EE * CC + h*DD;
        stride = CC;
    }

    // load Q, K as bf16 (row-major, k-contig)
    for (int i = tid; i < 96*16; i += 256) {
        int s = i >> 4, dp = i & 15;
        float2 q2 = *(const float2*)&Q[base + s*stride + dp*2];
        float2 k2 = *(const float2*)&Kb[base + s*stride + dp*2];
        sQ[s*20 + dp] = packbf(q2.x, q2.y);
        sK[s*20 + dp] = packbf(k2.x, k2.y);
    }
    // load V transposed: sVt[d][key], stride 98 bf16 (49 u32, odd -> conflict-free)
    for (int i = tid; i < 96*32; i += 256) {
        int s = i >> 5, d = i & 31;
        float v = V[base + s*stride + d];
        ((unsigned short*)sVt)[d*98 + s] = (unsigned short)packbf(v, 0.f);
    }
    if (TEMPORAL) {
        ; // sF used later for softmax scratch
    } else {
        // adj into sF (stride 97) and fp32 V column sums
        for (int i = tid; i < 96*96; i += 256)
            sF[(i/96)*97 + (i%96)] = adj[i];
        float ps = 0.f;
        for (int k2 = warp*12; k2 < warp*12 + 12; k2++)
            ps += V[base + k2*stride + lane];
        sPart[warp*32 + lane] = ps;
    }
    __syncthreads();

    if (!TEMPORAL) {
        if (tid < 32) {
            float cs = 0.f;
            #pragma unroll
            for (int p = 0; p < 8; p++) cs += sPart[p*32 + tid];
            sCol[tid] = cs;
        }
    }

    // S = Q K^T : 72 tiles (6 m x 12 n), 9 per warp; K-dim = 32 (2 steps)
    for (int t = warp; t < 72; t += 8) {
        int mi = t / 12, ni = t % 12;
        int m0 = mi*16, n0 = ni*8;
        float c0 = 0.f, c1 = 0.f, c2 = 0.f, c3 = 0.f;
        #pragma unroll
        for (int kh = 0; kh < 2; kh++) {
            unsigned a0 = sQ[(m0+g  )*20 + kh*8 + tig];
            unsigned a1 = sQ[(m0+g+8)*20 + kh*8 + tig];
            unsigned a2 = sQ[(m0+g  )*20 + kh*8 + tig + 4];
            unsigned a3 = sQ[(m0+g+8)*20 + kh*8 + tig + 4];
            unsigned b0 = sK[(n0+g)*20 + kh*8 + tig];
            unsigned b1 = sK[(n0+g)*20 + kh*8 + tig + 4];
            MMA16816(c0, c1, c2, c3, a0, a1, a2, a3, b0, b1);
        }
        if (TEMPORAL) {
            const float sc = 0.17677669529663687f;  // 1/sqrt(32)
            int r0 = m0+g, r1 = m0+g+8, cc = n0 + tig*2;
            sF[r0*97 + cc]     = c0*sc;
            sF[r0*97 + cc + 1] = c1*sc;
            sF[r1*97 + cc]     = c2*sc;
            sF[r1*97 + cc + 1] = c3*sc;
        } else {
            // u = s*adj*0.5 only (0.5 offset handled via colsum in O epilogue)
            int r0 = m0+g, r1 = m0+g+8, cc = n0 + tig*2;
            float t0 = c0 * sF[r0*97+cc]   * 0.5f;
            float t1 = c1 * sF[r0*97+cc+1] * 0.5f;
            float t2 = c2 * sF[r1*97+cc]   * 0.5f;
            float t3 = c3 * sF[r1*97+cc+1] * 0.5f;
            sS[r0*52 + ni*4 + tig] = packbf(t0, t1);
            sS[r1*52 + ni*4 + tig] = packbf(t2, t3);
        }
    }
    __syncthreads();

    if (TEMPORAL) {
        // softmax over rows (12 rows per warp), normalized fp32 back into sF
        for (int r = warp; r < 96; r += 8) {
            float v0 = sF[r*97+lane], v1 = sF[r*97+32+lane], v2 = sF[r*97+64+lane];
            float mx = fmaxf(v0, fmaxf(v1, v2));
            #pragma unroll
            for (int o = 16; o; o >>= 1) mx = fmaxf(mx, __shfl_xor_sync(0xffffffffu, mx, o));
            float e0 = expf(v0-mx), e1 = expf(v1-mx), e2 = expf(v2-mx);
            float s = warpSum(e0 + e1 + e2);
            float inv = 1.f / s;
            sF[r*97+lane] = e0*inv; sF[r*97+32+lane] = e1*inv; sF[r*97+64+lane] = e2*inv;
        }
        __syncthreads();
        // pack probabilities to bf16 sS
        for (int i = tid; i < 96*48; i += 256) {
            int r = i / 48, cp = i % 48;
            sS[r*52 + cp] = packbf(sF[r*97 + cp*2], sF[r*97 + cp*2 + 1]);
        }
        __syncthreads();
    }

    // O = S V : 24 tiles (6 m x 4 n), 3 per warp; K-dim = 96 (6 steps)
    #pragma unroll
    for (int tt = 0; tt < 3; tt++) {
        int t = warp*3 + tt;
        int mi = t >> 2, ni = t & 3;
        int m0 = mi*16, n0 = ni*8;
        float c0 = 0.f, c1 = 0.f, c2 = 0.f, c3 = 0.f;
        #pragma unroll
        for (int ks = 0; ks < 6; ks++) {
            unsigned a0 = sS[(m0+g  )*52 + ks*8 + tig];
            unsigned a1 = sS[(m0+g+8)*52 + ks*8 + tig];
            unsigned a2 = sS[(m0+g  )*52 + ks*8 + tig + 4];
            unsigned a3 = sS[(m0+g+8)*52 + ks*8 + tig + 4];
            unsigned b0 = sVt[(n0+g)*49 + ks*8 + tig];
            unsigned b1 = sVt[(n0+g)*49 + ks*8 + tig + 4];
            MMA16816(c0, c1, c2, c3, a0, a1, a2, a3, b0, b1);
        }
        int cc = n0 + tig*2;
        if (!TEMPORAL) {
            float ca = 0.5f * sCol[cc], cb = 0.5f * sCol[cc+1];
            c0 += ca; c1 += cb; c2 += ca; c3 += cb;
        }
        float2 o0; o0.x = c0; o0.y = c1;
        float2 o1; o1.x = c2; o1.y = c3;
        *(float2*)&O[base + (m0+g  )*stride + cc] = o0;
        *(float2*)&O[base + (m0+g+8)*stride + cc] = o1;
    }
}

// ---------------- K5: p=LN(P;s_n); x += xs + s_gamma*p; XA = LN(x; n2) ----------
__global__ void k_fuse1(const float* __restrict__ sng, const float* __restrict__ snb,
                        const float* __restrict__ sgam,
                        const float* __restrict__ n2g, const float* __restrict__ n2b) {
    int warp = threadIdx.x >> 5, lane = threadIdx.x & 31;
    int row = blockIdx.x * 8 + warp;
    int bidx = row*CC;
    float4 p0 = ((const float4*)(g_P+bidx))[lane], p1 = ((const float4*)(g_P+bidx))[lane+32];
    float pf[8] = {p0.x,p0.y,p0.z,p0.w,p1.x,p1.y,p1.z,p1.w};
    float s = 0.f;
    #pragma unroll
    for (int j = 0; j < 8; j++) s += pf[j];
    float m1 = warpSum(s) * (1.f/CC);
    float vs = 0.f;
    #pragma unroll
    for (int j = 0; j < 8; j++) { pf[j] -= m1; vs += pf[j]*pf[j]; }
    float r1 = rsqrtf(warpSum(vs) * (1.f/CC) + EPSI);
    float4 ga = ((const float4*)sng)[lane], gb = ((const float4*)sng)[lane+32];
    float4 ba = ((const float4*)snb)[lane], bb = ((const float4*)snb)[lane+32];
    float gf[8] = {ga.x,ga.y,ga.z,ga.w,gb.x,gb.y,gb.z,gb.w};
    float bf_[8] = {ba.x,ba.y,ba.z,ba.w,bb.x,bb.y,bb.z,bb.w};
    float gamma = sgam[0];
    float4 x0 = ((const float4*)(g_X+bidx))[lane],  x1 = ((const float4*)(g_X+bidx))[lane+32];
    float4 s0 = ((const float4*)(g_XA+bidx))[lane], s1 = ((const float4*)(g_XA+bidx))[lane+32];
    float xf[8] = {x0.x,x0.y,x0.z,x0.w,x1.x,x1.y,x1.z,x1.w};
    float sf[8] = {s0.x,s0.y,s0.z,s0.w,s1.x,s1.y,s1.z,s1.w};
    float xn[8];
    #pragma unroll
    for (int j = 0; j < 8; j++)
        xn[j] = xf[j] + sf[j] + gamma * (pf[j]*r1*gf[j] + bf_[j]);
    float4 w0 = {xn[0],xn[1],xn[2],xn[3]}, w1 = {xn[4],xn[5],xn[6],xn[7]};
    ((float4*)(g_X+bidx))[lane] = w0; ((float4*)(g_X+bidx))[lane+32] = w1;
    // second LN
    float s2 = 0.f;
    #pragma unroll
    for (int j = 0; j < 8; j++) s2 += xn[j];
    float m2 = warpSum(s2) * (1.f/CC);
    float vs2 = 0.f;
    #pragma unroll
    for (int j = 0; j < 8; j++) { xn[j] -= m2; vs2 += xn[j]*xn[j]; }
    float r2 = rsqrtf(warpSum(vs2) * (1.f/CC) + EPSI);
    float4 g2a = ((const float4*)n2g)[lane], g2b = ((const float4*)n2g)[lane+32];
    float4 b2a = ((const float4*)n2b)[lane], b2b = ((const float4*)n2b)[lane+32];
    float g2f[8] = {g2a.x,g2a.y,g2a.z,g2a.w,g2b.x,g2b.y,g2b.z,g2b.w};
    float b2f[8] = {b2a.x,b2a.y,b2a.z,b2a.w,b2b.x,b2b.y,b2b.z,b2b.w};
    float o[8];
    #pragma unroll
    for (int j = 0; j < 8; j++) o[j] = xn[j]*r2*g2f[j] + b2f[j];
    float4 q0 = {o[0],o[1],o[2],o[3]}, q1 = {o[4],o[5],o[6],o[7]};
    ((float4*)(g_XA+bidx))[lane] = q0; ((float4*)(g_XA+bidx))[lane+32] = q1;
}

// ---------------- K9: x += t_gamma*P; XA = LN(x; n3) ----------------
__global__ void k_fuse2(const float* __restrict__ tgam,
                        const float* __restrict__ n3g, const float* __restrict__ n3b) {
    int warp = threadIdx.x >> 5, lane = threadIdx.x & 31;
    int row = blockIdx.x * 8 + warp;
    int bidx = row*CC;
    float gamma = tgam[0];
    float4 p0 = ((const float4*)(g_P+bidx))[lane], p1 = ((const float4*)(g_P+bidx))[lane+32];
    float4 x0 = ((const float4*)(g_X+bidx))[lane], x1 = ((const float4*)(g_X+bidx))[lane+32];
    float xn[8] = {x0.x + gamma*p0.x, x0.y + gamma*p0.y, x0.z + gamma*p0.z, x0.w + gamma*p0.w,
                   x1.x + gamma*p1.x, x1.y + gamma*p1.y, x1.z + gamma*p1.z, x1.w + gamma*p1.w};
    float4 w0 = {xn[0],xn[1],xn[2],xn[3]}, w1 = {xn[4],xn[5],xn[6],xn[7]};
    ((float4*)(g_X+bidx))[lane] = w0; ((float4*)(g_X+bidx))[lane+32] = w1;
    float s = 0.f;
    #pragma unroll
    for (int j = 0; j < 8; j++) s += xn[j];
    float m = warpSum(s) * (1.f/CC);
    float vs = 0.f;
    #pragma unroll
    for (int j = 0; j < 8; j++) { xn[j] -= m; vs += xn[j]*xn[j]; }
    float r = rsqrtf(warpSum(vs) * (1.f/CC) + EPSI);
    float4 ga = ((const float4*)n3g)[lane], gb = ((const float4*)n3g)[lane+32];
    float4 ba = ((const float4*)n3b)[lane], bb = ((const float4*)n3b)[lane+32];
    float gf[8] = {ga.x,ga.y,ga.z,ga.w,gb.x,gb.y,gb.z,gb.w};
    float bf_[8] = {ba.x,ba.y,ba.z,ba.w,bb.x,bb.y,bb.z,bb.w};
    float o[8];
    #pragma unroll
    for (int j = 0; j < 8; j++) o[j] = xn[j]*r*gf[j] + bf_[j];
    float4 q0 = {o[0],o[1],o[2],o[3]}, q1 = {o[4],o[5],o[6],o[7]};
    ((float4*)(g_XA+bidx))[lane] = q0; ((float4*)(g_XA+bidx))[lane+32] = q1;
}

// ---------------- K12: temporal downsample (T=96 -> 48, w=0.5 exactly) ----------
__global__ void k_down(float* __restrict__ out) {
    int i = blockIdx.x * blockDim.x + threadIdx.x;
    const float4* X4 = (const float4*)g_X;
    const int EC4 = EE*CC/4;
    int ec = i % EC4;
    int rest = i / EC4;
    int t2 = rest % 48;
    int b  = rest / 48;
    int in0 = (b*96 + 2*t2) * EC4 + ec;
    float4 a = X4[in0], c = X4[in0 + EC4];
    float4 o;
    o.x = 0.5f*(a.x + c.x); o.y = 0.5f*(a.y + c.y);
    o.z = 0.5f*(a.z + c.z); o.w = 0.5f*(a.w + c.w);
    ((float4*)out)[i] = o;
}

// ---------------- host ----------------
extern "C" void kernel_launch(void* const* d_in, const int* in_sizes, int n_in,
                              void* d_out, int out_size) {
    const float* x    = (const float*)d_in[0];
    const float* adj  = (const float*)d_in[1];
    const float* n1g  = (const float*)d_in[2];
    const float* n1b  = (const float*)d_in[3];
    const float* swq  = (const float*)d_in[4];
    const float* swk  = (const float*)d_in[5];
    const float* swv  = (const float*)d_in[6];
    const float* swp  = (const float*)d_in[7];
    const float* sbp  = (const float*)d_in[8];
    const float* sng  = (const float*)d_in[9];
    const float* snb  = (const float*)d_in[10];
    const float* sgam = (const float*)d_in[11];
    const float* n2g  = (const float*)d_in[12];
    const float* n2b  = (const float*)d_in[13];
    const float* twq  = (const float*)d_in[14];
    const float* twk  = (const float*)d_in[15];
    const float* twv  = (const float*)d_in[16];
    const float* twp  = (const float*)d_in[17];
    const float* tbp  = (const float*)d_in[18];
    const float* tgam = (const float*)d_in[19];
    const float* n3g  = (const float*)d_in[20];
    const float* n3b  = (const float*)d_in[21];
    const float* mw1  = (const float*)d_in[22];
    const float* mb1  = (const float*)d_in[23];
    const float* mw2  = (const float*)d_in[24];
    const float* mb2  = (const float*)d_in[25];

    float *X, *XA, *Q, *K, *V, *O, *P, *Hd;
    cudaGetSymbolAddress((void**)&X,  g_X);
    cudaGetSymbolAddress((void**)&XA, g_XA);
    cudaGetSymbolAddress((void**)&Q,  g_Q);
    cudaGetSymbolAddress((void**)&K,  g_K);
    cudaGetSymbolAddress((void**)&V,  g_V);
    cudaGetSymbolAddress((void**)&O,  g_O);
    cudaGetSymbolAddress((void**)&P,  g_P);
    cudaGetSymbolAddress((void**)&Hd, g_Hd);

    cudaFuncSetAttribute(attn_mma<false>, cudaFuncAttributeMaxDynamicSharedMemorySize, ATTN_SMEM);
    cudaFuncSetAttribute(attn_mma<true>,  cudaFuncAttributeMaxDynamicSharedMemorySize, ATTN_SMEM);

    dim3 g256(256/128, NROWS/128);    // (2, 576)
    dim3 g1024(1024/128, NROWS/128);  // (8, 576)

    // ---- spatial block ----
    k_ln1<<<NROWS/8, 256>>>(x, n1g, n1b);
    hgemm_k<0><<<g256, 256>>>(XA, swq, nullptr, nullptr, Q, NROWS, CC, CC);
    hgemm_k<0><<<g256, 256>>>(XA, swk, nullptr, nullptr, K, NROWS, CC, CC);
    hgemm_k<0><<<g256, 256>>>(XA, swv, nullptr, nullptr, V, NROWS, CC, CC);
    attn_mma<false><<<dim3(BB*TT, HH), 256, ATTN_SMEM>>>(Q, K, V, O, adj);
    hgemm_k<1><<<g256, 256>>>(O, swp, sbp, nullptr, P, NROWS, CC, CC);
    k_fuse1<<<NROWS/8, 256>>>(sng, snb, sgam, n2g, n2b);

    // ---- temporal block ----
    hgemm_k<0><<<g256, 256>>>(XA, twq, nullptr, nullptr, Q, NROWS, CC, CC);
    hgemm_k<0><<<g256, 256>>>(XA, twk, nullptr, nullptr, K, NROWS, CC, CC);
    hgemm_k<0><<<g256, 256>>>(XA, twv, nullptr, nullptr, V, NROWS, CC, CC);
    attn_mma<true><<<dim3(BB*EE, HH), 256, ATTN_SMEM>>>(Q, K, V, O, nullptr);
    hgemm_k<1><<<g256, 256>>>(O, twp, tbp, nullptr, P, NROWS, CC, CC);
    k_fuse2<<<NROWS/8, 256>>>(tgam, n3g, n3b);

    // ---- MLP ----
    hgemm_k<2><<<g1024, 256>>>(XA, mw1, mb1, nullptr, Hd, NROWS, HIDN, CC);
    hgemm_k<3><<<g256, 256>>>(Hd, mw2, mb2, X, X, NROWS, CC, HIDN);

    // ---- downsample ----
    k_down<<<(BB*48*EE*CC/4)/256, 256>>>((float*)d_out);

    (void)in_sizes; (void)n_in; (void)out_size;
}

// round 8
// speedup vs baseline: 4.1564x; 1.3650x over previous
#include <cuda_runtime.h>
#include <cuda_bf16.h>
#include <math.h>

#define BB 8
#define TT 96
#define EE 96
#define CC 256
#define HH 8
#define DD 32
#define HIDN 1024
#define NROWS (BB*TT*EE)   /* 73728 */
#define EPSI 1e-5f

// ---------------- scratch (static device globals; no allocations) ----------------
__device__ float g_X [NROWS*CC];            // running residual x (fp32)
__device__ float g_XA[NROWS*CC];            // xs fp32 (residual add in fuse1)
__device__ __nv_bfloat16 g_XAb[NROWS*CC];   // LN outputs, bf16 (GEMM A)
__device__ __nv_bfloat16 g_Qb [NROWS*CC];
__device__ __nv_bfloat16 g_Kb [NROWS*CC];
__device__ __nv_bfloat16 g_Vb [NROWS*CC];
__device__ __nv_bfloat16 g_Ob [NROWS*CC];
__device__ __nv_bfloat16 g_Pb [NROWS*CC];
__device__ __nv_bfloat16 g_Hb [NROWS*HIDN];
// weights bf16: swq,swk,swv,swp,twq,twk,twv,twp, mw1, mw2
#define W_SQ 0
#define W_SK 65536
#define W_SV 131072
#define W_SP 196608
#define W_TQ 262144
#define W_TK 327680
#define W_TV 393216
#define W_TP 458752
#define W_M1 524288
#define W_M2 786432
#define W_TOT 1048576
__device__ __nv_bfloat16 g_WB[W_TOT];

__device__ __forceinline__ float warpSum(float v) {
    #pragma unroll
    for (int o = 16; o; o >>= 1) v += __shfl_xor_sync(0xffffffffu, v, o);
    return v;
}
__device__ __forceinline__ unsigned packbf(float lo, float hi) {
    unsigned r;
    asm("cvt.rn.bf16x2.f32 %0, %1, %2;" : "=r"(r) : "f"(hi), "f"(lo));
    return r;
}
__device__ __forceinline__ void unpack4(uint2 v, float* f) {
    __nv_bfloat162* h = (__nv_bfloat162*)&v;
    float2 a = __bfloat1622float2(h[0]); float2 b = __bfloat1622float2(h[1]);
    f[0]=a.x; f[1]=a.y; f[2]=b.x; f[3]=b.y;
}

#define MMA16816(c0,c1,c2,c3,a0,a1,a2,a3,b0,b1) \
    asm volatile( \
        "mma.sync.aligned.m16n8k16.row.col.f32.bf16.bf16.f32 " \
        "{%0,%1,%2,%3},{%4,%5,%6,%7},{%8,%9},{%0,%1,%2,%3};" \
        : "+f"(c0), "+f"(c1), "+f"(c2), "+f"(c3) \
        : "r"(a0), "r"(a1), "r"(a2), "r"(a3), "r"(b0), "r"(b1))

// ---------------- K0: weights -> bf16 ----------------
__global__ void k_wconv(const float* w0, const float* w1, const float* w2, const float* w3,
                        const float* w4, const float* w5, const float* w6, const float* w7,
                        const float* w8, const float* w9) {
    const float* srcs[10] = {w0,w1,w2,w3,w4,w5,w6,w7,w8,w9};
    const int offs[10] = {W_SQ,W_SK,W_SV,W_SP,W_TQ,W_TK,W_TV,W_TP,W_M1,W_M2};
    int gid = blockIdx.x * blockDim.x + threadIdx.x;       // 131072 threads
    int e0 = gid * 8;
    int seg;
    if (e0 < W_M1) seg = e0 >> 16;
    else if (e0 < W_M2) seg = 8;
    else seg = 9;
    const float* s = srcs[seg] + (e0 - offs[seg]);
    float4 a = *(const float4*)s, b = *(const float4*)(s + 4);
    unsigned* d = (unsigned*)(g_WB + e0);
    d[0] = packbf(a.x, a.y); d[1] = packbf(a.z, a.w);
    d[2] = packbf(b.x, b.y); d[3] = packbf(b.z, b.w);
}

// ---------------- K1: X = x ; XA = LN(x; n1) fp32 + bf16 ----------------
__global__ void k_ln1(const float* __restrict__ x,
                      const float* __restrict__ g, const float* __restrict__ b) {
    int warp = threadIdx.x >> 5, lane = threadIdx.x & 31;
    int row = blockIdx.x * 8 + warp;
    const float4* xr = (const float4*)(x + row*CC);
    float4 a0 = xr[lane], a1 = xr[lane+32];
    float4* Xr = (float4*)(g_X + row*CC);
    Xr[lane] = a0; Xr[lane+32] = a1;
    float f[8] = {a0.x,a0.y,a0.z,a0.w,a1.x,a1.y,a1.z,a1.w};
    float s = 0.f;
    #pragma unroll
    for (int j = 0; j < 8; j++) s += f[j];
    float m = warpSum(s) * (1.f/CC);
    float vs = 0.f;
    #pragma unroll
    for (int j = 0; j < 8; j++) { f[j] -= m; vs += f[j]*f[j]; }
    float r = rsqrtf(warpSum(vs) * (1.f/CC) + EPSI);
    float4 ga = ((const float4*)g)[lane], gb = ((const float4*)g)[lane+32];
    float4 ba = ((const float4*)b)[lane], bb = ((const float4*)b)[lane+32];
    float gf[8] = {ga.x,ga.y,ga.z,ga.w,gb.x,gb.y,gb.z,gb.w};
    float bf_[8] = {ba.x,ba.y,ba.z,ba.w,bb.x,bb.y,bb.z,bb.w};
    float o[8];
    #pragma unroll
    for (int j = 0; j < 8; j++) o[j] = f[j]*r*gf[j] + bf_[j];
    float4* Or = (float4*)(g_XA + row*CC);
    float4 o0 = {o[0],o[1],o[2],o[3]}, o1 = {o[4],o[5],o[6],o[7]};
    Or[lane] = o0; Or[lane+32] = o1;
    uint2* Ob2 = (uint2*)(g_XAb + row*CC);
    uint2 p0; p0.x = packbf(o[0],o[1]); p0.y = packbf(o[2],o[3]);
    uint2 p1; p1.x = packbf(o[4],o[5]); p1.y = packbf(o[6],o[7]);
    Ob2[lane] = p0; Ob2[lane+32] = p1;
}

// ---------------- bf16 GEMM 128x128x32 (A,B bf16; EPI epilogue; OUTBF out dtype) --
#define A_STRIDE_U32 20   /* 40 bf16 per row (32 data + 8 pad) */
#define B_STRIDE_U16 132  /* 128 data + 4 pad */

template<int EPI, int OUTBF>
__global__ void __launch_bounds__(256)
hgemm_k(const __nv_bfloat16* __restrict__ A, const __nv_bfloat16* __restrict__ B,
        const float* __restrict__ bias, const float* __restrict__ Res,
        void* __restrict__ Cout, int M, int N, int K) {
    __shared__ unsigned AsU[2][128 * A_STRIDE_U32];
    __shared__ unsigned BsU[2][(32 * B_STRIDE_U16) / 2];

    int tid  = threadIdx.x;
    int bm   = blockIdx.y * 128, bn = blockIdx.x * 128;
    int lane = tid & 31, warp = tid >> 5;
    int wm   = (warp & 1) * 64, wn = (warp >> 1) * 32;
    int g    = lane >> 2, tig = lane & 3;

    int rowA = tid >> 2, colA = (tid & 3) * 8;   // A: 128x32 bf16, 2 passes of 64 rows
    int rowB = tid >> 4, colB = (tid & 15) * 8;  // B: 32x128 bf16, 2 passes of 16 rows

    float acc[4][4][4];
    #pragma unroll
    for (int i = 0; i < 4; i++)
        #pragma unroll
        for (int j = 0; j < 4; j++)
            #pragma unroll
            for (int k = 0; k < 4; k++) acc[i][j][k] = 0.f;

    uint4 pa[2], pb[2];
    int kTiles = K >> 5;

    #pragma unroll
    for (int p = 0; p < 2; p++)
        pa[p] = *(const uint4*)&A[(bm + rowA + p*64) * K + colA];
    #pragma unroll
    for (int p = 0; p < 2; p++)
        pb[p] = *(const uint4*)&B[(rowB + p*16) * N + bn + colB];
    #pragma unroll
    for (int p = 0; p < 2; p++) {
        unsigned* d = &AsU[0][(rowA + p*64) * A_STRIDE_U32 + (tid & 3) * 4];
        d[0] = pa[p].x; d[1] = pa[p].y; d[2] = pa[p].z; d[3] = pa[p].w;
    }
    #pragma unroll
    for (int p = 0; p < 2; p++) {
        unsigned* d = &BsU[0][((rowB + p*16) * B_STRIDE_U16 + colB) >> 1];
        d[0] = pb[p].x; d[1] = pb[p].y; d[2] = pb[p].z; d[3] = pb[p].w;
    }
    __syncthreads();

    for (int kt = 0; kt < kTiles; ++kt) {
        int buf = kt & 1;
        bool hasNext = (kt + 1 < kTiles);
        if (hasNext) {
            int kOff = (kt + 1) * 32;
            #pragma unroll
            for (int p = 0; p < 2; p++)
                pa[p] = *(const uint4*)&A[(bm + rowA + p*64) * K + kOff + colA];
            #pragma unroll
            for (int p = 0; p < 2; p++)
                pb[p] = *(const uint4*)&B[(kOff + rowB + p*16) * N + bn + colB];
        }

        #pragma unroll
        for (int kh = 0; kh < 2; ++kh) {
            unsigned af[4][4];
            unsigned bfr[4][2];
            #pragma unroll
            for (int mi = 0; mi < 4; ++mi) {
                const unsigned* p = &AsU[buf][(wm + mi*16 + g) * A_STRIDE_U32 + kh*8 + tig];
                af[mi][0] = p[0];
                af[mi][1] = p[8 * A_STRIDE_U32];
                af[mi][2] = p[4];
                af[mi][3] = p[8 * A_STRIDE_U32 + 4];
            }
            const unsigned short* Bs16 = (const unsigned short*)BsU[buf];
            #pragma unroll
            for (int ni = 0; ni < 4; ++ni) {
                int ccol = wn + ni*8 + g;
                int k0 = kh*16 + tig*2;
                unsigned lo0 = Bs16[ k0      * B_STRIDE_U16 + ccol];
                unsigned hi0 = Bs16[(k0 + 1) * B_STRIDE_U16 + ccol];
                unsigned lo1 = Bs16[(k0 + 8) * B_STRIDE_U16 + ccol];
                unsigned hi1 = Bs16[(k0 + 9) * B_STRIDE_U16 + ccol];
                bfr[ni][0] = lo0 | (hi0 << 16);
                bfr[ni][1] = lo1 | (hi1 << 16);
            }
            #pragma unroll
            for (int mi = 0; mi < 4; ++mi)
                #pragma unroll
                for (int ni = 0; ni < 4; ++ni)
                    MMA16816(acc[mi][ni][0], acc[mi][ni][1], acc[mi][ni][2], acc[mi][ni][3],
                             af[mi][0], af[mi][1], af[mi][2], af[mi][3],
                             bfr[ni][0], bfr[ni][1]);
        }

        if (hasNext) {
            int nb = buf ^ 1;
            #pragma unroll
            for (int p = 0; p < 2; p++) {
                unsigned* d = &AsU[nb][(rowA + p*64) * A_STRIDE_U32 + (tid & 3) * 4];
                d[0] = pa[p].x; d[1] = pa[p].y; d[2] = pa[p].z; d[3] = pa[p].w;
            }
            #pragma unroll
            for (int p = 0; p < 2; p++) {
                unsigned* d = &BsU[nb][((rowB + p*16) * B_STRIDE_U16 + colB) >> 1];
                d[0] = pb[p].x; d[1] = pb[p].y; d[2] = pb[p].z; d[3] = pb[p].w;
            }
            __syncthreads();
        }
    }

    #pragma unroll
    for (int mi = 0; mi < 4; ++mi) {
        int r0 = bm + wm + mi*16 + g;
        #pragma unroll
        for (int ni = 0; ni < 4; ++ni) {
            int c = bn + wn + ni*8 + tig*2;
            float v0 = acc[mi][ni][0], v1 = acc[mi][ni][1];
            float v2 = acc[mi][ni][2], v3 = acc[mi][ni][3];
            if (EPI >= 1) {
                float b0 = bias[c], b1 = bias[c+1];
                v0 += b0; v1 += b1; v2 += b0; v3 += b1;
            }
            if (EPI == 2) {
                v0 = 0.5f * v0 * (1.f + erff(v0 * 0.70710678118654752f));
                v1 = 0.5f * v1 * (1.f + erff(v1 * 0.70710678118654752f));
                v2 = 0.5f * v2 * (1.f + erff(v2 * 0.70710678118654752f));
                v3 = 0.5f * v3 * (1.f + erff(v3 * 0.70710678118654752f));
            }
            if (EPI == 3) {
                float2 ra = *(const float2*)&Res[r0 * N + c];
                float2 rb = *(const float2*)&Res[(r0 + 8) * N + c];
                v0 += ra.x; v1 += ra.y; v2 += rb.x; v3 += rb.y;
            }
            if (OUTBF) {
                unsigned* C32 = (unsigned*)Cout;
                C32[(r0 * N + c) >> 1]       = packbf(v0, v1);
                C32[((r0 + 8) * N + c) >> 1] = packbf(v2, v3);
            } else {
                float* Cf = (float*)Cout;
                float2 o0; o0.x = v0; o0.y = v1;
                float2 o1; o1.x = v2; o1.y = v3;
                *(float2*)&Cf[r0 * N + c]       = o0;
                *(float2*)&Cf[(r0 + 8) * N + c] = o1;
            }
        }
    }
}

// ---------------- attention via bf16 mma (bf16 in, bf16 out) ----------------
#define O_SQ   0                  /* 96 x 20 u32 */
#define O_SK   1920
#define O_SVT  3840               /* 32 x 49 u32 (V transposed, stride 98 bf16) */
#define O_SS   5408               /* 96 x 52 u32 */
#define O_PART 10400
#define O_COL  10656
#define O_SF   10688              /* 96 x 97 fp32 */
#define ATTN_U32 (O_SF + 96*97)
#define ATTN_SMEM (ATTN_U32 * 4)

template<bool TEMPORAL>
__global__ void __launch_bounds__(256)
attn_mma(const __nv_bfloat16* __restrict__ Q, const __nv_bfloat16* __restrict__ Kb,
         const __nv_bfloat16* __restrict__ V, __nv_bfloat16* __restrict__ O,
         const float* __restrict__ adj) {
    extern __shared__ unsigned su[];
    unsigned* sQ  = su + O_SQ;
    unsigned* sK  = su + O_SK;
    unsigned* sVt = su + O_SVT;
    unsigned* sS  = su + O_SS;
    float* sPart  = (float*)(su + O_PART);
    float* sCol   = (float*)(su + O_COL);
    float* sF     = (float*)(su + O_SF);

    int tid = threadIdx.x, lane = tid & 31, warp = tid >> 5;
    int g = lane >> 2, tig = lane & 3;
    int h = blockIdx.y;
    int base, stride;
    if (TEMPORAL) {
        int b = blockIdx.x / EE, e = blockIdx.x % EE;
        base = (b*TT*EE + e)*CC + h*DD;
        stride = EE*CC;
    } else {
        base = blockIdx.x * EE * CC + h*DD;
        stride = CC;
    }

    // Q, K: 96 rows x 32 bf16 = 4 uint4 per row
    for (int i = tid; i < 96*4; i += 256) {
        int s = i >> 2, part = i & 3;
        uint4 q4 = *(const uint4*)&Q[base + s*stride + part*8];
        uint4 k4 = *(const uint4*)&Kb[base + s*stride + part*8];
        unsigned* dq = &sQ[s*20 + part*4];
        dq[0]=q4.x; dq[1]=q4.y; dq[2]=q4.z; dq[3]=q4.w;
        unsigned* dk = &sK[s*20 + part*4];
        dk[0]=k4.x; dk[1]=k4.y; dk[2]=k4.z; dk[3]=k4.w;
    }
    // V transposed (u16 copy)
    const unsigned short* Vs = (const unsigned short*)V;
    for (int i = tid; i < 96*32; i += 256) {
        int s = i >> 5, d = i & 31;
        ((unsigned short*)sVt)[d*98 + s] = Vs[base + s*stride + d];
    }
    if (!TEMPORAL) {
        for (int i = tid; i < 96*96; i += 256)
            sF[(i/96)*97 + (i%96)] = adj[i];
        float ps = 0.f;
        for (int k2 = warp*12; k2 < warp*12 + 12; k2++)
            ps += __bfloat162float(V[base + k2*stride + lane]);
        sPart[warp*32 + lane] = ps;
    }
    __syncthreads();

    if (!TEMPORAL) {
        if (tid < 32) {
            float cs = 0.f;
            #pragma unroll
            for (int p = 0; p < 8; p++) cs += sPart[p*32 + tid];
            sCol[tid] = cs;
        }
    }

    // S = Q K^T
    for (int t = warp; t < 72; t += 8) {
        int mi = t / 12, ni = t % 12;
        int m0 = mi*16, n0 = ni*8;
        float c0 = 0.f, c1 = 0.f, c2 = 0.f, c3 = 0.f;
        #pragma unroll
        for (int kh = 0; kh < 2; kh++) {
            unsigned a0 = sQ[(m0+g  )*20 + kh*8 + tig];
            unsigned a1 = sQ[(m0+g+8)*20 + kh*8 + tig];
            unsigned a2 = sQ[(m0+g  )*20 + kh*8 + tig + 4];
            unsigned a3 = sQ[(m0+g+8)*20 + kh*8 + tig + 4];
            unsigned b0 = sK[(n0+g)*20 + kh*8 + tig];
            unsigned b1 = sK[(n0+g)*20 + kh*8 + tig + 4];
            MMA16816(c0, c1, c2, c3, a0, a1, a2, a3, b0, b1);
        }
        if (TEMPORAL) {
            const float sc = 0.17677669529663687f;
            int r0 = m0+g, r1 = m0+g+8, cc = n0 + tig*2;
            sF[r0*97 + cc]     = c0*sc;
            sF[r0*97 + cc + 1] = c1*sc;
            sF[r1*97 + cc]     = c2*sc;
            sF[r1*97 + cc + 1] = c3*sc;
        } else {
            int r0 = m0+g, r1 = m0+g+8, cc = n0 + tig*2;
            float t0 = c0 * sF[r0*97+cc]   * 0.5f;
            float t1 = c1 * sF[r0*97+cc+1] * 0.5f;
            float t2 = c2 * sF[r1*97+cc]   * 0.5f;
            float t3 = c3 * sF[r1*97+cc+1] * 0.5f;
            sS[r0*52 + ni*4 + tig] = packbf(t0, t1);
            sS[r1*52 + ni*4 + tig] = packbf(t2, t3);
        }
    }
    __syncthreads();

    if (TEMPORAL) {
        for (int r = warp; r < 96; r += 8) {
            float v0 = sF[r*97+lane], v1 = sF[r*97+32+lane], v2 = sF[r*97+64+lane];
            float mx = fmaxf(v0, fmaxf(v1, v2));
            #pragma unroll
            for (int o = 16; o; o >>= 1) mx = fmaxf(mx, __shfl_xor_sync(0xffffffffu, mx, o));
            float e0 = expf(v0-mx), e1 = expf(v1-mx), e2 = expf(v2-mx);
            float s = warpSum(e0 + e1 + e2);
            float inv = 1.f / s;
            sF[r*97+lane] = e0*inv; sF[r*97+32+lane] = e1*inv; sF[r*97+64+lane] = e2*inv;
        }
        __syncthreads();
        for (int i = tid; i < 96*48; i += 256) {
            int r = i / 48, cp = i % 48;
            sS[r*52 + cp] = packbf(sF[r*97 + cp*2], sF[r*97 + cp*2 + 1]);
        }
        __syncthreads();
    }

    // O = S V
    unsigned* O32 = (unsigned*)O;
    #pragma unroll
    for (int tt = 0; tt < 3; tt++) {
        int t = warp*3 + tt;
        int mi = t >> 2, ni = t & 3;
        int m0 = mi*16, n0 = ni*8;
        float c0 = 0.f, c1 = 0.f, c2 = 0.f, c3 = 0.f;
        #pragma unroll
        for (int ks = 0; ks < 6; ks++) {
            unsigned a0 = sS[(m0+g  )*52 + ks*8 + tig];
            unsigned a1 = sS[(m0+g+8)*52 + ks*8 + tig];
            unsigned a2 = sS[(m0+g  )*52 + ks*8 + tig + 4];
            unsigned a3 = sS[(m0+g+8)*52 + ks*8 + tig + 4];
            unsigned b0 = sVt[(n0+g)*49 + ks*8 + tig];
            unsigned b1 = sVt[(n0+g)*49 + ks*8 + tig + 4];
            MMA16816(c0, c1, c2, c3, a0, a1, a2, a3, b0, b1);
        }
        int cc = n0 + tig*2;
        if (!TEMPORAL) {
            float ca = 0.5f * sCol[cc], cb = 0.5f * sCol[cc+1];
            c0 += ca; c1 += cb; c2 += ca; c3 += cb;
        }
        O32[(base + (m0+g  )*stride + cc) >> 1] = packbf(c0, c1);
        O32[(base + (m0+g+8)*stride + cc) >> 1] = packbf(c2, c3);
    }
}

// ---------------- K5: p=LN(Pb;s_n); x += xs + s_gamma*p; XAb = LN(x; n2) --------
__global__ void k_fuse1(const float* __restrict__ sng, const float* __restrict__ snb,
                        const float* __restrict__ sgam,
                        const float* __restrict__ n2g, const float* __restrict__ n2b) {
    int warp = threadIdx.x >> 5, lane = threadIdx.x & 31;
    int row = blockIdx.x * 8 + warp;
    int bidx = row*CC;
    uint2 pv0 = ((const uint2*)(g_Pb+bidx))[lane], pv1 = ((const uint2*)(g_Pb+bidx))[lane+32];
    float pf[8];
    unpack4(pv0, pf); unpack4(pv1, pf+4);
    float s = 0.f;
    #pragma unroll
    for (int j = 0; j < 8; j++) s += pf[j];
    float m1 = warpSum(s) * (1.f/CC);
    float vs = 0.f;
    #pragma unroll
    for (int j = 0; j < 8; j++) { pf[j] -= m1; vs += pf[j]*pf[j]; }
    float r1 = rsqrtf(warpSum(vs) * (1.f/CC) + EPSI);
    float4 ga = ((const float4*)sng)[lane], gb = ((const float4*)sng)[lane+32];
    float4 ba = ((const float4*)snb)[lane], bb = ((const float4*)snb)[lane+32];
    float gf[8] = {ga.x,ga.y,ga.z,ga.w,gb.x,gb.y,gb.z,gb.w};
    float bf_[8] = {ba.x,ba.y,ba.z,ba.w,bb.x,bb.y,bb.z,bb.w};
    float gamma = sgam[0];
    float4 x0 = ((const float4*)(g_X+bidx))[lane],  x1 = ((const float4*)(g_X+bidx))[lane+32];
    float4 s0 = ((const float4*)(g_XA+bidx))[lane], s1 = ((const float4*)(g_XA+bidx))[lane+32];
    float xf[8] = {x0.x,x0.y,x0.z,x0.w,x1.x,x1.y,x1.z,x1.w};
    float sf[8] = {s0.x,s0.y,s0.z,s0.w,s1.x,s1.y,s1.z,s1.w};
    float xn[8];
    #pragma unroll
    for (int j = 0; j < 8; j++)
        xn[j] = xf[j] + sf[j] + gamma * (pf[j]*r1*gf[j] + bf_[j]);
    float4 w0 = {xn[0],xn[1],xn[2],xn[3]}, w1 = {xn[4],xn[5],xn[6],xn[7]};
    ((float4*)(g_X+bidx))[lane] = w0; ((float4*)(g_X+bidx))[lane+32] = w1;
    float s2 = 0.f;
    #pragma unroll
    for (int j = 0; j < 8; j++) s2 += xn[j];
    float m2 = warpSum(s2) * (1.f/CC);
    float vs2 = 0.f;
    #pragma unroll
    for (int j = 0; j < 8; j++) { xn[j] -= m2; vs2 += xn[j]*xn[j]; }
    float r2 = rsqrtf(warpSum(vs2) * (1.f/CC) + EPSI);
    float4 g2a = ((const float4*)n2g)[lane], g2b = ((const float4*)n2g)[lane+32];
    float4 b2a = ((const float4*)n2b)[lane], b2b = ((const float4*)n2b)[lane+32];
    float g2f[8] = {g2a.x,g2a.y,g2a.z,g2a.w,g2b.x,g2b.y,g2b.z,g2b.w};
    float b2f[8] = {b2a.x,b2a.y,b2a.z,b2a.w,b2b.x,b2b.y,b2b.z,b2b.w};
    float o[8];
    #pragma unroll
    for (int j = 0; j < 8; j++) o[j] = xn[j]*r2*g2f[j] + b2f[j];
    uint2* Ob2 = (uint2*)(g_XAb + bidx);
    uint2 q0; q0.x = packbf(o[0],o[1]); q0.y = packbf(o[2],o[3]);
    uint2 q1; q1.x = packbf(o[4],o[5]); q1.y = packbf(o[6],o[7]);
    Ob2[lane] = q0; Ob2[lane+32] = q1;
}

// ---------------- K9: x += t_gamma*Pb; XAb = LN(x; n3) ----------------
__global__ void k_fuse2(const float* __restrict__ tgam,
                        const float* __restrict__ n3g, const float* __restrict__ n3b) {
    int warp = threadIdx.x >> 5, lane = threadIdx.x & 31;
    int row = blockIdx.x * 8 + warp;
    int bidx = row*CC;
    float gamma = tgam[0];
    uint2 pv0 = ((const uint2*)(g_Pb+bidx))[lane], pv1 = ((const uint2*)(g_Pb+bidx))[lane+32];
    float pf[8];
    unpack4(pv0, pf); unpack4(pv1, pf+4);
    float4 x0 = ((const float4*)(g_X+bidx))[lane], x1 = ((const float4*)(g_X+bidx))[lane+32];
    float xn[8] = {x0.x + gamma*pf[0], x0.y + gamma*pf[1], x0.z + gamma*pf[2], x0.w + gamma*pf[3],
                   x1.x + gamma*pf[4], x1.y + gamma*pf[5], x1.z + gamma*pf[6], x1.w + gamma*pf[7]};
    float4 w0 = {xn[0],xn[1],xn[2],xn[3]}, w1 = {xn[4],xn[5],xn[6],xn[7]};
    ((float4*)(g_X+bidx))[lane] = w0; ((float4*)(g_X+bidx))[lane+32] = w1;
    float s = 0.f;
    #pragma unroll
    for (int j = 0; j < 8; j++) s += xn[j];
    float m = warpSum(s) * (1.f/CC);
    float vs = 0.f;
    #pragma unroll
    for (int j = 0; j < 8; j++) { xn[j] -= m; vs += xn[j]*xn[j]; }
    float r = rsqrtf(warpSum(vs) * (1.f/CC) + EPSI);
    float4 ga = ((const float4*)n3g)[lane], gb = ((const float4*)n3g)[lane+32];
    float4 ba = ((const float4*)n3b)[lane], bb = ((const float4*)n3b)[lane+32];
    float gf[8] = {ga.x,ga.y,ga.z,ga.w,gb.x,gb.y,gb.z,gb.w};
    float bf_[8] = {ba.x,ba.y,ba.z,ba.w,bb.x,bb.y,bb.z,bb.w};
    float o[8];
    #pragma unroll
    for (int j = 0; j < 8; j++) o[j] = xn[j]*r*gf[j] + bf_[j];
    uint2* Ob2 = (uint2*)(g_XAb + bidx);
    uint2 q0; q0.x = packbf(o[0],o[1]); q0.y = packbf(o[2],o[3]);
    uint2 q1; q1.x = packbf(o[4],o[5]); q1.y = packbf(o[6],o[7]);
    Ob2[lane] = q0; Ob2[lane+32] = q1;
}

// ---------------- K12: temporal downsample ----------------
__global__ void k_down(float* __restrict__ out) {
    int i = blockIdx.x * blockDim.x + threadIdx.x;
    const float4* X4 = (const float4*)g_X;
    const int EC4 = EE*CC/4;
    int ec = i % EC4;
    int rest = i / EC4;
    int t2 = rest % 48;
    int b  = rest / 48;
    int in0 = (b*96 + 2*t2) * EC4 + ec;
    float4 a = X4[in0], c = X4[in0 + EC4];
    float4 o;
    o.x = 0.5f*(a.x + c.x); o.y = 0.5f*(a.y + c.y);
    o.z = 0.5f*(a.z + c.z); o.w = 0.5f*(a.w + c.w);
    ((float4*)out)[i] = o;
}

// ---------------- host ----------------
extern "C" void kernel_launch(void* const* d_in, const int* in_sizes, int n_in,
                              void* d_out, int out_size) {
    const float* x    = (const float*)d_in[0];
    const float* adj  = (const float*)d_in[1];
    const float* n1g  = (const float*)d_in[2];
    const float* n1b  = (const float*)d_in[3];
    const float* swq  = (const float*)d_in[4];
    const float* swk  = (const float*)d_in[5];
    const float* swv  = (const float*)d_in[6];
    const float* swp  = (const float*)d_in[7];
    const float* sbp  = (const float*)d_in[8];
    const float* sng  = (const float*)d_in[9];
    const float* snb  = (const float*)d_in[10];
    const float* sgam = (const float*)d_in[11];
    const float* n2g  = (const float*)d_in[12];
    const float* n2b  = (const float*)d_in[13];
    const float* twq  = (const float*)d_in[14];
    const float* twk  = (const float*)d_in[15];
    const float* twv  = (const float*)d_in[16];
    const float* twp  = (const float*)d_in[17];
    const float* tbp  = (const float*)d_in[18];
    const float* tgam = (const float*)d_in[19];
    const float* n3g  = (const float*)d_in[20];
    const float* n3b  = (const float*)d_in[21];
    const float* mw1  = (const float*)d_in[22];
    const float* mb1  = (const float*)d_in[23];
    const float* mw2  = (const float*)d_in[24];
    const float* mb2  = (const float*)d_in[25];

    float *X;
    __nv_bfloat16 *XAb, *Qb, *Kb, *Vb, *Ob, *Pb, *Hb, *WB;
    cudaGetSymbolAddress((void**)&X,   g_X);
    cudaGetSymbolAddress((void**)&XAb, g_XAb);
    cudaGetSymbolAddress((void**)&Qb,  g_Qb);
    cudaGetSymbolAddress((void**)&Kb,  g_Kb);
    cudaGetSymbolAddress((void**)&Vb,  g_Vb);
    cudaGetSymbolAddress((void**)&Ob,  g_Ob);
    cudaGetSymbolAddress((void**)&Pb,  g_Pb);
    cudaGetSymbolAddress((void**)&Hb,  g_Hb);
    cudaGetSymbolAddress((void**)&WB,  g_WB);

    cudaFuncSetAttribute(attn_mma<false>, cudaFuncAttributeMaxDynamicSharedMemorySize, ATTN_SMEM);
    cudaFuncSetAttribute(attn_mma<true>,  cudaFuncAttributeMaxDynamicSharedMemorySize, ATTN_SMEM);

    dim3 g256(256/128, NROWS/128);    // (2, 576)
    dim3 g1024(1024/128, NROWS/128);  // (8, 576)

    k_wconv<<<512, 256>>>(swq, swk, swv, swp, twq, twk, twv, twp, mw1, mw2);

    // ---- spatial block ----
    k_ln1<<<NROWS/8, 256>>>(x, n1g, n1b);
    hgemm_k<0,1><<<g256, 256>>>(XAb, WB+W_SQ, nullptr, nullptr, Qb, NROWS, CC, CC);
    hgemm_k<0,1><<<g256, 256>>>(XAb, WB+W_SK, nullptr, nullptr, Kb, NROWS, CC, CC);
    hgemm_k<0,1><<<g256, 256>>>(XAb, WB+W_SV, nullptr, nullptr, Vb, NROWS, CC, CC);
    attn_mma<false><<<dim3(BB*TT, HH), 256, ATTN_SMEM>>>(Qb, Kb, Vb, Ob, adj);
    hgemm_k<1,1><<<g256, 256>>>(Ob, WB+W_SP, sbp, nullptr, Pb, NROWS, CC, CC);
    k_fuse1<<<NROWS/8, 256>>>(sng, snb, sgam, n2g, n2b);

    // ---- temporal block ----
    hgemm_k<0,1><<<g256, 256>>>(XAb, WB+W_TQ, nullptr, nullptr, Qb, NROWS, CC, CC);
    hgemm_k<0,1><<<g256, 256>>>(XAb, WB+W_TK, nullptr, nullptr, Kb, NROWS, CC, CC);
    hgemm_k<0,1><<<g256, 256>>>(XAb, WB+W_TV, nullptr, nullptr, Vb, NROWS, CC, CC);
    attn_mma<true><<<dim3(BB*EE, HH), 256, ATTN_SMEM>>>(Qb, Kb, Vb, Ob, nullptr);
    hgemm_k<1,1><<<g256, 256>>>(Ob, WB+W_TP, tbp, nullptr, Pb, NROWS, CC, CC);
    k_fuse2<<<NROWS/8, 256>>>(tgam, n3g, n3b);

    // ---- MLP ----
    hgemm_k<2,1><<<g1024, 256>>>(XAb, WB+W_M1, mb1, nullptr, Hb, NROWS, HIDN, CC);
    hgemm_k<3,0><<<g256, 256>>>(Hb, WB+W_M2, mb2, X, X, NROWS, CC, HIDN);

    // ---- downsample ----
    k_down<<<(BB*48*EE*CC/4)/256, 256>>>((float*)d_out);

    (void)in_sizes; (void)n_in; (void)out_size;
}

// round 9
// speedup vs baseline: 4.2094x; 1.0128x over previous
#include <cuda_runtime.h>
#include <cuda_bf16.h>
#include <math.h>

#define BB 8
#define TT 96
#define EE 96
#define CC 256
#define HH 8
#define DD 32
#define HIDN 1024
#define NROWS (BB*TT*EE)   /* 73728 */
#define EPSI 1e-5f

// ---------------- scratch (static device globals; no allocations) ----------------
__device__ float g_X [NROWS*CC];            // running residual x (fp32)
__device__ float g_XA[NROWS*CC];            // xs fp32 (residual add in fuse1)
__device__ __nv_bfloat16 g_XAb[NROWS*CC];   // LN outputs, bf16 (GEMM A)
__device__ __nv_bfloat16 g_QKVb[NROWS*768]; // fused QKV output
__device__ __nv_bfloat16 g_Ob [NROWS*CC];
__device__ __nv_bfloat16 g_Pb [NROWS*CC];
__device__ __nv_bfloat16 g_Hb [NROWS*HIDN];
// transposed bf16 weights: [N][K] each
#define W_SQ 0
#define W_SK 65536
#define W_SV 131072
#define W_SP 196608
#define W_TQ 262144
#define W_TK 327680
#define W_TV 393216
#define W_TP 458752
#define W_M1 524288
#define W_M2 786432
#define W_TOT 1048576
__device__ __nv_bfloat16 g_WB[W_TOT];

__device__ __forceinline__ float warpSum(float v) {
    #pragma unroll
    for (int o = 16; o; o >>= 1) v += __shfl_xor_sync(0xffffffffu, v, o);
    return v;
}
__device__ __forceinline__ unsigned packbf(float lo, float hi) {
    unsigned r;
    asm("cvt.rn.bf16x2.f32 %0, %1, %2;" : "=r"(r) : "f"(hi), "f"(lo));
    return r;
}
__device__ __forceinline__ void unpack4(uint2 v, float* f) {
    __nv_bfloat162* h = (__nv_bfloat162*)&v;
    float2 a = __bfloat1622float2(h[0]); float2 b = __bfloat1622float2(h[1]);
    f[0]=a.x; f[1]=a.y; f[2]=b.x; f[3]=b.y;
}

#define MMA16816(c0,c1,c2,c3,a0,a1,a2,a3,b0,b1) \
    asm volatile( \
        "mma.sync.aligned.m16n8k16.row.col.f32.bf16.bf16.f32 " \
        "{%0,%1,%2,%3},{%4,%5,%6,%7},{%8,%9},{%0,%1,%2,%3};" \
        : "+f"(c0), "+f"(c1), "+f"(c2), "+f"(c3) \
        : "r"(a0), "r"(a1), "r"(a2), "r"(a3), "r"(b0), "r"(b1))

// ---------------- K0: weights -> transposed bf16 [N][K] ----------------
__global__ void k_wconv(const float* w0, const float* w1, const float* w2, const float* w3,
                        const float* w4, const float* w5, const float* w6, const float* w7,
                        const float* w8, const float* w9) {
    const float* srcs[10] = {w0,w1,w2,w3,w4,w5,w6,w7,w8,w9};
    const int offs[10] = {W_SQ,W_SK,W_SV,W_SP,W_TQ,W_TK,W_TV,W_TP,W_M1,W_M2};
    const int KsA[10]  = {256,256,256,256,256,256,256,256,256,1024};
    const int NsA[10]  = {256,256,256,256,256,256,256,256,1024,256};
    int gid = blockIdx.x * blockDim.x + threadIdx.x;   // 524288 threads
    int e0 = gid * 2;
    int seg;
    if (e0 < W_M1) seg = e0 >> 16;
    else if (e0 < W_M2) seg = 8;
    else seg = 9;
    int Ks = KsA[seg], Ns = NsA[seg];
    int rel2 = (e0 - offs[seg]) >> 1;
    int n = rel2 % Ns;
    int k0 = (rel2 / Ns) * 2;
    const float* s = srcs[seg];
    float lo = s[k0*Ns + n], hi = s[(k0+1)*Ns + n];
    *(unsigned*)(g_WB + offs[seg] + n*Ks + k0) = packbf(lo, hi);
}

// ---------------- K1: X = x ; XA = LN(x; n1) fp32 + bf16 ----------------
__global__ void k_ln1(const float* __restrict__ x,
                      const float* __restrict__ g, const float* __restrict__ b) {
    int warp = threadIdx.x >> 5, lane = threadIdx.x & 31;
    int row = blockIdx.x * 8 + warp;
    const float4* xr = (const float4*)(x + row*CC);
    float4 a0 = xr[lane], a1 = xr[lane+32];
    float4* Xr = (float4*)(g_X + row*CC);
    Xr[lane] = a0; Xr[lane+32] = a1;
    float f[8] = {a0.x,a0.y,a0.z,a0.w,a1.x,a1.y,a1.z,a1.w};
    float s = 0.f;
    #pragma unroll
    for (int j = 0; j < 8; j++) s += f[j];
    float m = warpSum(s) * (1.f/CC);
    float vs = 0.f;
    #pragma unroll
    for (int j = 0; j < 8; j++) { f[j] -= m; vs += f[j]*f[j]; }
    float r = rsqrtf(warpSum(vs) * (1.f/CC) + EPSI);
    float4 ga = ((const float4*)g)[lane], gb = ((const float4*)g)[lane+32];
    float4 ba = ((const float4*)b)[lane], bb = ((const float4*)b)[lane+32];
    float gf[8] = {ga.x,ga.y,ga.z,ga.w,gb.x,gb.y,gb.z,gb.w};
    float bf_[8] = {ba.x,ba.y,ba.z,ba.w,bb.x,bb.y,bb.z,bb.w};
    float o[8];
    #pragma unroll
    for (int j = 0; j < 8; j++) o[j] = f[j]*r*gf[j] + bf_[j];
    float4* Or = (float4*)(g_XA + row*CC);
    float4 o0 = {o[0],o[1],o[2],o[3]}, o1 = {o[4],o[5],o[6],o[7]};
    Or[lane] = o0; Or[lane+32] = o1;
    uint2* Ob2 = (uint2*)(g_XAb + row*CC);
    uint2 p0; p0.x = packbf(o[0],o[1]); p0.y = packbf(o[2],o[3]);
    uint2 p1; p1.x = packbf(o[4],o[5]); p1.y = packbf(o[6],o[7]);
    Ob2[lane] = p0; Ob2[lane+32] = p1;
}

// ---------------- bf16 GEMM 128x128x32; B pre-transposed [N][K] ----------------
#define T_STRIDE_U32 20   /* 40 bf16 per row (32 data + 8 pad) */

template<int EPI, int OUTBF>
__global__ void __launch_bounds__(256)
hgemm_k(const __nv_bfloat16* __restrict__ A, const __nv_bfloat16* __restrict__ Bt,
        const float* __restrict__ bias, const float* __restrict__ Res,
        void* __restrict__ Cout, int M, int N, int K) {
    __shared__ unsigned AsU[2][128 * T_STRIDE_U32];
    __shared__ unsigned BsU[2][128 * T_STRIDE_U32];

    int tid  = threadIdx.x;
    int bm   = blockIdx.y * 128, bn = blockIdx.x * 128;
    int lane = tid & 31, warp = tid >> 5;
    int wm   = (warp & 1) * 64, wn = (warp >> 1) * 32;
    int g    = lane >> 2, tig = lane & 3;

    int rowT = tid >> 2, colT = (tid & 3) * 8;   // 128x32 bf16 tile, 2 passes of 64 rows

    float acc[4][4][4];
    #pragma unroll
    for (int i = 0; i < 4; i++)
        #pragma unroll
        for (int j = 0; j < 4; j++)
            #pragma unroll
            for (int k = 0; k < 4; k++) acc[i][j][k] = 0.f;

    uint4 pa[2], pb[2];
    int kTiles = K >> 5;

    #pragma unroll
    for (int p = 0; p < 2; p++) {
        pa[p] = *(const uint4*)&A [(bm + rowT + p*64) * K + colT];
        pb[p] = *(const uint4*)&Bt[(bn + rowT + p*64) * K + colT];
    }
    #pragma unroll
    for (int p = 0; p < 2; p++) {
        unsigned* d = &AsU[0][(rowT + p*64) * T_STRIDE_U32 + (tid & 3) * 4];
        d[0] = pa[p].x; d[1] = pa[p].y; d[2] = pa[p].z; d[3] = pa[p].w;
        unsigned* e = &BsU[0][(rowT + p*64) * T_STRIDE_U32 + (tid & 3) * 4];
        e[0] = pb[p].x; e[1] = pb[p].y; e[2] = pb[p].z; e[3] = pb[p].w;
    }
    __syncthreads();

    for (int kt = 0; kt < kTiles; ++kt) {
        int buf = kt & 1;
        bool hasNext = (kt + 1 < kTiles);
        if (hasNext) {
            int kOff = (kt + 1) * 32;
            #pragma unroll
            for (int p = 0; p < 2; p++) {
                pa[p] = *(const uint4*)&A [(bm + rowT + p*64) * K + kOff + colT];
                pb[p] = *(const uint4*)&Bt[(bn + rowT + p*64) * K + kOff + colT];
            }
        }

        #pragma unroll
        for (int kh = 0; kh < 2; ++kh) {
            unsigned af[4][4];
            unsigned bfr[4][2];
            #pragma unroll
            for (int mi = 0; mi < 4; ++mi) {
                const unsigned* p = &AsU[buf][(wm + mi*16 + g) * T_STRIDE_U32 + kh*8 + tig];
                af[mi][0] = p[0];
                af[mi][1] = p[8 * T_STRIDE_U32];
                af[mi][2] = p[4];
                af[mi][3] = p[8 * T_STRIDE_U32 + 4];
            }
            #pragma unroll
            for (int ni = 0; ni < 4; ++ni) {
                const unsigned* q = &BsU[buf][(wn + ni*8 + g) * T_STRIDE_U32 + kh*8 + tig];
                bfr[ni][0] = q[0];
                bfr[ni][1] = q[4];
            }
            #pragma unroll
            for (int mi = 0; mi < 4; ++mi)
                #pragma unroll
                for (int ni = 0; ni < 4; ++ni)
                    MMA16816(acc[mi][ni][0], acc[mi][ni][1], acc[mi][ni][2], acc[mi][ni][3],
                             af[mi][0], af[mi][1], af[mi][2], af[mi][3],
                             bfr[ni][0], bfr[ni][1]);
        }

        if (hasNext) {
            int nb = buf ^ 1;
            #pragma unroll
            for (int p = 0; p < 2; p++) {
                unsigned* d = &AsU[nb][(rowT + p*64) * T_STRIDE_U32 + (tid & 3) * 4];
                d[0] = pa[p].x; d[1] = pa[p].y; d[2] = pa[p].z; d[3] = pa[p].w;
                unsigned* e = &BsU[nb][(rowT + p*64) * T_STRIDE_U32 + (tid & 3) * 4];
                e[0] = pb[p].x; e[1] = pb[p].y; e[2] = pb[p].z; e[3] = pb[p].w;
            }
            __syncthreads();
        }
    }

    #pragma unroll
    for (int mi = 0; mi < 4; ++mi) {
        int r0 = bm + wm + mi*16 + g;
        #pragma unroll
        for (int ni = 0; ni < 4; ++ni) {
            int c = bn + wn + ni*8 + tig*2;
            float v0 = acc[mi][ni][0], v1 = acc[mi][ni][1];
            float v2 = acc[mi][ni][2], v3 = acc[mi][ni][3];
            if (EPI >= 1) {
                float b0 = bias[c], b1 = bias[c+1];
                v0 += b0; v1 += b1; v2 += b0; v3 += b1;
            }
            if (EPI == 2) {
                v0 = 0.5f * v0 * (1.f + erff(v0 * 0.70710678118654752f));
                v1 = 0.5f * v1 * (1.f + erff(v1 * 0.70710678118654752f));
                v2 = 0.5f * v2 * (1.f + erff(v2 * 0.70710678118654752f));
                v3 = 0.5f * v3 * (1.f + erff(v3 * 0.70710678118654752f));
            }
            if (EPI == 3) {
                float2 ra = *(const float2*)&Res[r0 * N + c];
                float2 rb = *(const float2*)&Res[(r0 + 8) * N + c];
                v0 += ra.x; v1 += ra.y; v2 += rb.x; v3 += rb.y;
            }
            if (OUTBF) {
                unsigned* C32 = (unsigned*)Cout;
                C32[(r0 * N + c) >> 1]       = packbf(v0, v1);
                C32[((r0 + 8) * N + c) >> 1] = packbf(v2, v3);
            } else {
                float* Cf = (float*)Cout;
                float2 o0; o0.x = v0; o0.y = v1;
                float2 o1; o1.x = v2; o1.y = v3;
                *(float2*)&Cf[r0 * N + c]       = o0;
                *(float2*)&Cf[(r0 + 8) * N + c] = o1;
            }
        }
    }
}

// ---------------- attention via bf16 mma (reads fused QKV [NROWS][768]) --------
#define O_SQ   0                  /* 96 x 20 u32 */
#define O_SK   1920
#define O_SVT  3840               /* 32 x 49 u32 (V transposed, stride 98 bf16) */
#define O_SS   5408               /* 96 x 52 u32 */
#define O_PART 10400
#define O_COL  10656
#define O_SF   10688              /* 96 x 97 fp32 */
#define ATTN_U32 (O_SF + 96*97)
#define ATTN_SMEM (ATTN_U32 * 4)

template<bool TEMPORAL>
__global__ void __launch_bounds__(256)
attn_mma(const __nv_bfloat16* __restrict__ QKV, __nv_bfloat16* __restrict__ O,
         const float* __restrict__ adj) {
    extern __shared__ unsigned su[];
    unsigned* sQ  = su + O_SQ;
    unsigned* sK  = su + O_SK;
    unsigned* sVt = su + O_SVT;
    unsigned* sS  = su + O_SS;
    float* sPart  = (float*)(su + O_PART);
    float* sCol   = (float*)(su + O_COL);
    float* sF     = (float*)(su + O_SF);

    int tid = threadIdx.x, lane = tid & 31, warp = tid >> 5;
    int g = lane >> 2, tig = lane & 3;
    int h = blockIdx.y;
    int row0, qstride, ostride;
    if (TEMPORAL) {
        int b = blockIdx.x / EE, e = blockIdx.x % EE;
        row0 = b*TT*EE + e;
        qstride = EE*768; ostride = EE*CC;
    } else {
        row0 = blockIdx.x * EE;
        qstride = 768; ostride = CC;
    }
    int qbase = row0*768 + h*DD;
    int obase = row0*CC  + h*DD;
    const __nv_bfloat16* Qp = QKV + qbase;
    const __nv_bfloat16* Kp = QKV + qbase + 256;
    const __nv_bfloat16* Vp = QKV + qbase + 512;

    // Q, K: 96 rows x 32 bf16 = 4 uint4 per row
    for (int i = tid; i < 96*4; i += 256) {
        int s = i >> 2, part = i & 3;
        uint4 q4 = *(const uint4*)&Qp[s*qstride + part*8];
        uint4 k4 = *(const uint4*)&Kp[s*qstride + part*8];
        unsigned* dq = &sQ[s*20 + part*4];
        dq[0]=q4.x; dq[1]=q4.y; dq[2]=q4.z; dq[3]=q4.w;
        unsigned* dk = &sK[s*20 + part*4];
        dk[0]=k4.x; dk[1]=k4.y; dk[2]=k4.z; dk[3]=k4.w;
    }
    // V transposed (u16 copy)
    const unsigned short* Vs = (const unsigned short*)Vp;
    for (int i = tid; i < 96*32; i += 256) {
        int s = i >> 5, d = i & 31;
        ((unsigned short*)sVt)[d*98 + s] = Vs[s*qstride + d];
    }
    if (!TEMPORAL) {
        for (int i = tid; i < 96*96; i += 256)
            sF[(i/96)*97 + (i%96)] = adj[i];
        float ps = 0.f;
        for (int k2 = warp*12; k2 < warp*12 + 12; k2++)
            ps += __bfloat162float(Vp[k2*qstride + lane]);
        sPart[warp*32 + lane] = ps;
    }
    __syncthreads();

    if (!TEMPORAL) {
        if (tid < 32) {
            float cs = 0.f;
            #pragma unroll
            for (int p = 0; p < 8; p++) cs += sPart[p*32 + tid];
            sCol[tid] = cs;
        }
    }

    // S = Q K^T
    for (int t = warp; t < 72; t += 8) {
        int mi = t / 12, ni = t % 12;
        int m0 = mi*16, n0 = ni*8;
        float c0 = 0.f, c1 = 0.f, c2 = 0.f, c3 = 0.f;
        #pragma unroll
        for (int kh = 0; kh < 2; kh++) {
            unsigned a0 = sQ[(m0+g  )*20 + kh*8 + tig];
            unsigned a1 = sQ[(m0+g+8)*20 + kh*8 + tig];
            unsigned a2 = sQ[(m0+g  )*20 + kh*8 + tig + 4];
            unsigned a3 = sQ[(m0+g+8)*20 + kh*8 + tig + 4];
            unsigned b0 = sK[(n0+g)*20 + kh*8 + tig];
            unsigned b1 = sK[(n0+g)*20 + kh*8 + tig + 4];
            MMA16816(c0, c1, c2, c3, a0, a1, a2, a3, b0, b1);
        }
        if (TEMPORAL) {
            const float sc = 0.17677669529663687f;
            int r0 = m0+g, r1 = m0+g+8, cc = n0 + tig*2;
            sF[r0*97 + cc]     = c0*sc;
            sF[r0*97 + cc + 1] = c1*sc;
            sF[r1*97 + cc]     = c2*sc;
            sF[r1*97 + cc + 1] = c3*sc;
        } else {
            int r0 = m0+g, r1 = m0+g+8, cc = n0 + tig*2;
            float t0 = c0 * sF[r0*97+cc]   * 0.5f;
            float t1 = c1 * sF[r0*97+cc+1] * 0.5f;
            float t2 = c2 * sF[r1*97+cc]   * 0.5f;
            float t3 = c3 * sF[r1*97+cc+1] * 0.5f;
            sS[r0*52 + ni*4 + tig] = packbf(t0, t1);
            sS[r1*52 + ni*4 + tig] = packbf(t2, t3);
        }
    }
    __syncthreads();

    if (TEMPORAL) {
        for (int r = warp; r < 96; r += 8) {
            float v0 = sF[r*97+lane], v1 = sF[r*97+32+lane], v2 = sF[r*97+64+lane];
            float mx = fmaxf(v0, fmaxf(v1, v2));
            #pragma unroll
            for (int o = 16; o; o >>= 1) mx = fmaxf(mx, __shfl_xor_sync(0xffffffffu, mx, o));
            float e0 = expf(v0-mx), e1 = expf(v1-mx), e2 = expf(v2-mx);
            float s = warpSum(e0 + e1 + e2);
            float inv = 1.f / s;
            sF[r*97+lane] = e0*inv; sF[r*97+32+lane] = e1*inv; sF[r*97+64+lane] = e2*inv;
        }
        __syncthreads();
        for (int i = tid; i < 96*48; i += 256) {
            int r = i / 48, cp = i % 48;
            sS[r*52 + cp] = packbf(sF[r*97 + cp*2], sF[r*97 + cp*2 + 1]);
        }
        __syncthreads();
    }

    // O = S V
    unsigned* O32 = (unsigned*)O;
    #pragma unroll
    for (int tt = 0; tt < 3; tt++) {
        int t = warp*3 + tt;
        int mi = t >> 2, ni = t & 3;
        int m0 = mi*16, n0 = ni*8;
        float c0 = 0.f, c1 = 0.f, c2 = 0.f, c3 = 0.f;
        #pragma unroll
        for (int ks = 0; ks < 6; ks++) {
            unsigned a0 = sS[(m0+g  )*52 + ks*8 + tig];
            unsigned a1 = sS[(m0+g+8)*52 + ks*8 + tig];
            unsigned a2 = sS[(m0+g  )*52 + ks*8 + tig + 4];
            unsigned a3 = sS[(m0+g+8)*52 + ks*8 + tig + 4];
            unsigned b0 = sVt[(n0+g)*49 + ks*8 + tig];
            unsigned b1 = sVt[(n0+g)*49 + ks*8 + tig + 4];
            MMA16816(c0, c1, c2, c3, a0, a1, a2, a3, b0, b1);
        }
        int cc = n0 + tig*2;
        if (!TEMPORAL) {
            float ca = 0.5f * sCol[cc], cb = 0.5f * sCol[cc+1];
            c0 += ca; c1 += cb; c2 += ca; c3 += cb;
        }
        O32[(obase + (m0+g  )*ostride + cc) >> 1] = packbf(c0, c1);
        O32[(obase + (m0+g+8)*ostride + cc) >> 1] = packbf(c2, c3);
    }
}

// ---------------- K5: p=LN(Pb;s_n); x += xs + s_gamma*p; XAb = LN(x; n2) --------
__global__ void k_fuse1(const float* __restrict__ sng, const float* __restrict__ snb,
                        const float* __restrict__ sgam,
                        const float* __restrict__ n2g, const float* __restrict__ n2b) {
    int warp = threadIdx.x >> 5, lane = threadIdx.x & 31;
    int row = blockIdx.x * 8 + warp;
    int bidx = row*CC;
    uint2 pv0 = ((const uint2*)(g_Pb+bidx))[lane], pv1 = ((const uint2*)(g_Pb+bidx))[lane+32];
    float pf[8];
    unpack4(pv0, pf); unpack4(pv1, pf+4);
    float s = 0.f;
    #pragma unroll
    for (int j = 0; j < 8; j++) s += pf[j];
    float m1 = warpSum(s) * (1.f/CC);
    float vs = 0.f;
    #pragma unroll
    for (int j = 0; j < 8; j++) { pf[j] -= m1; vs += pf[j]*pf[j]; }
    float r1 = rsqrtf(warpSum(vs) * (1.f/CC) + EPSI);
    float4 ga = ((const float4*)sng)[lane], gb = ((const float4*)sng)[lane+32];
    float4 ba = ((const float4*)snb)[lane], bb = ((const float4*)snb)[lane+32];
    float gf[8] = {ga.x,ga.y,ga.z,ga.w,gb.x,gb.y,gb.z,gb.w};
    float bf_[8] = {ba.x,ba.y,ba.z,ba.w,bb.x,bb.y,bb.z,bb.w};
    float gamma = sgam[0];
    float4 x0 = ((const float4*)(g_X+bidx))[lane],  x1 = ((const float4*)(g_X+bidx))[lane+32];
    float4 s0 = ((const float4*)(g_XA+bidx))[lane], s1 = ((const float4*)(g_XA+bidx))[lane+32];
    float xf[8] = {x0.x,x0.y,x0.z,x0.w,x1.x,x1.y,x1.z,x1.w};
    float sf[8] = {s0.x,s0.y,s0.z,s0.w,s1.x,s1.y,s1.z,s1.w};
    float xn[8];
    #pragma unroll
    for (int j = 0; j < 8; j++)
        xn[j] = xf[j] + sf[j] + gamma * (pf[j]*r1*gf[j] + bf_[j]);
    float4 w0 = {xn[0],xn[1],xn[2],xn[3]}, w1 = {xn[4],xn[5],xn[6],xn[7]};
    ((float4*)(g_X+bidx))[lane] = w0; ((float4*)(g_X+bidx))[lane+32] = w1;
    float s2 = 0.f;
    #pragma unroll
    for (int j = 0; j < 8; j++) s2 += xn[j];
    float m2 = warpSum(s2) * (1.f/CC);
    float vs2 = 0.f;
    #pragma unroll
    for (int j = 0; j < 8; j++) { xn[j] -= m2; vs2 += xn[j]*xn[j]; }
    float r2 = rsqrtf(warpSum(vs2) * (1.f/CC) + EPSI);
    float4 g2a = ((const float4*)n2g)[lane], g2b = ((const float4*)n2g)[lane+32];
    float4 b2a = ((const float4*)n2b)[lane], b2b = ((const float4*)n2b)[lane+32];
    float g2f[8] = {g2a.x,g2a.y,g2a.z,g2a.w,g2b.x,g2b.y,g2b.z,g2b.w};
    float b2f[8] = {b2a.x,b2a.y,b2a.z,b2a.w,b2b.x,b2b.y,b2b.z,b2b.w};
    float o[8];
    #pragma unroll
    for (int j = 0; j < 8; j++) o[j] = xn[j]*r2*g2f[j] + b2f[j];
    uint2* Ob2 = (uint2*)(g_XAb + bidx);
    uint2 q0; q0.x = packbf(o[0],o[1]); q0.y = packbf(o[2],o[3]);
    uint2 q1; q1.x = packbf(o[4],o[5]); q1.y = packbf(o[6],o[7]);
    Ob2[lane] = q0; Ob2[lane+32] = q1;
}

// ---------------- K9: x += t_gamma*Pb; XAb = LN(x; n3) ----------------
__global__ void k_fuse2(const float* __restrict__ tgam,
                        const float* __restrict__ n3g, const float* __restrict__ n3b) {
    int warp = threadIdx.x >> 5, lane = threadIdx.x & 31;
    int row = blockIdx.x * 8 + warp;
    int bidx = row*CC;
    float gamma = tgam[0];
    uint2 pv0 = ((const uint2*)(g_Pb+bidx))[lane], pv1 = ((const uint2*)(g_Pb+bidx))[lane+32];
    float pf[8];
    unpack4(pv0, pf); unpack4(pv1, pf+4);
    float4 x0 = ((const float4*)(g_X+bidx))[lane], x1 = ((const float4*)(g_X+bidx))[lane+32];
    float xn[8] = {x0.x + gamma*pf[0], x0.y + gamma*pf[1], x0.z + gamma*pf[2], x0.w + gamma*pf[3],
                   x1.x + gamma*pf[4], x1.y + gamma*pf[5], x1.z + gamma*pf[6], x1.w + gamma*pf[7]};
    float4 w0 = {xn[0],xn[1],xn[2],xn[3]}, w1 = {xn[4],xn[5],xn[6],xn[7]};
    ((float4*)(g_X+bidx))[lane] = w0; ((float4*)(g_X+bidx))[lane+32] = w1;
    float s = 0.f;
    #pragma unroll
    for (int j = 0; j < 8; j++) s += xn[j];
    float m = warpSum(s) * (1.f/CC);
    float vs = 0.f;
    #pragma unroll
    for (int j = 0; j < 8; j++) { xn[j] -= m; vs += xn[j]*xn[j]; }
    float r = rsqrtf(warpSum(vs) * (1.f/CC) + EPSI);
    float4 ga = ((const float4*)n3g)[lane], gb = ((const float4*)n3g)[lane+32];
    float4 ba = ((const float4*)n3b)[lane], bb = ((const float4*)n3b)[lane+32];
    float gf[8] = {ga.x,ga.y,ga.z,ga.w,gb.x,gb.y,gb.z,gb.w};
    float bf_[8] = {ba.x,ba.y,ba.z,ba.w,bb.x,bb.y,bb.z,bb.w};
    float o[8];
    #pragma unroll
    for (int j = 0; j < 8; j++) o[j] = xn[j]*r*gf[j] + bf_[j];
    uint2* Ob2 = (uint2*)(g_XAb + bidx);
    uint2 q0; q0.x = packbf(o[0],o[1]); q0.y = packbf(o[2],o[3]);
    uint2 q1; q1.x = packbf(o[4],o[5]); q1.y = packbf(o[6],o[7]);
    Ob2[lane] = q0; Ob2[lane+32] = q1;
}

// ---------------- K12: temporal downsample ----------------
__global__ void k_down(float* __restrict__ out) {
    int i = blockIdx.x * blockDim.x + threadIdx.x;
    const float4* X4 = (const float4*)g_X;
    const int EC4 = EE*CC/4;
    int ec = i % EC4;
    int rest = i / EC4;
    int t2 = rest % 48;
    int b  = rest / 48;
    int in0 = (b*96 + 2*t2) * EC4 + ec;
    float4 a = X4[in0], c = X4[in0 + EC4];
    float4 o;
    o.x = 0.5f*(a.x + c.x); o.y = 0.5f*(a.y + c.y);
    o.z = 0.5f*(a.z + c.z); o.w = 0.5f*(a.w + c.w);
    ((float4*)out)[i] = o;
}

// ---------------- host ----------------
extern "C" void kernel_launch(void* const* d_in, const int* in_sizes, int n_in,
                              void* d_out, int out_size) {
    const float* x    = (const float*)d_in[0];
    const float* adj  = (const float*)d_in[1];
    const float* n1g  = (const float*)d_in[2];
    const float* n1b  = (const float*)d_in[3];
    const float* swq  = (const float*)d_in[4];
    const float* swk  = (const float*)d_in[5];
    const float* swv  = (const float*)d_in[6];
    const float* swp  = (const float*)d_in[7];
    const float* sbp  = (const float*)d_in[8];
    const float* sng  = (const float*)d_in[9];
    const float* snb  = (const float*)d_in[10];
    const float* sgam = (const float*)d_in[11];
    const float* n2g  = (const float*)d_in[12];
    const float* n2b  = (const float*)d_in[13];
    const float* twq  = (const float*)d_in[14];
    const float* twk  = (const float*)d_in[15];
    const float* twv  = (const float*)d_in[16];
    const float* twp  = (const float*)d_in[17];
    const float* tbp  = (const float*)d_in[18];
    const float* tgam = (const float*)d_in[19];
    const float* n3g  = (const float*)d_in[20];
    const float* n3b  = (const float*)d_in[21];
    const float* mw1  = (const float*)d_in[22];
    const float* mb1  = (const float*)d_in[23];
    const float* mw2  = (const float*)d_in[24];
    const float* mb2  = (const float*)d_in[25];

    float *X;
    __nv_bfloat16 *XAb, *QKVb, *Ob, *Pb, *Hb, *WB;
    cudaGetSymbolAddress((void**)&X,    g_X);
    cudaGetSymbolAddress((void**)&XAb,  g_XAb);
    cudaGetSymbolAddress((void**)&QKVb, g_QKVb);
    cudaGetSymbolAddress((void**)&Ob,   g_Ob);
    cudaGetSymbolAddress((void**)&Pb,   g_Pb);
    cudaGetSymbolAddress((void**)&Hb,   g_Hb);
    cudaGetSymbolAddress((void**)&WB,   g_WB);

    cudaFuncSetAttribute(attn_mma<false>, cudaFuncAttributeMaxDynamicSharedMemorySize, ATTN_SMEM);
    cudaFuncSetAttribute(attn_mma<true>,  cudaFuncAttributeMaxDynamicSharedMemorySize, ATTN_SMEM);

    dim3 g256(2, NROWS/128);     // N=256
    dim3 g768(6, NROWS/128);     // N=768 fused QKV
    dim3 g1024(8, NROWS/128);    // N=1024

    k_wconv<<<2048, 256>>>(swq, swk, swv, swp, twq, twk, twv, twp, mw1, mw2);

    // ---- spatial block ----
    k_ln1<<<NROWS/8, 256>>>(x, n1g, n1b);
    hgemm_k<0,1><<<g768, 256>>>(XAb, WB+W_SQ, nullptr, nullptr, QKVb, NROWS, 768, CC);
    attn_mma<false><<<dim3(BB*TT, HH), 256, ATTN_SMEM>>>(QKVb, Ob, adj);
    hgemm_k<1,1><<<g256, 256>>>(Ob, WB+W_SP, sbp, nullptr, Pb, NROWS, CC, CC);
    k_fuse1<<<NROWS/8, 256>>>(sng, snb, sgam, n2g, n2b);

    // ---- temporal block ----
    hgemm_k<0,1><<<g768, 256>>>(XAb, WB+W_TQ, nullptr, nullptr, QKVb, NROWS, 768, CC);
    attn_mma<true><<<dim3(BB*EE, HH), 256, ATTN_SMEM>>>(QKVb, Ob, nullptr);
    hgemm_k<1,1><<<g256, 256>>>(Ob, WB+W_TP, tbp, nullptr, Pb, NROWS, CC, CC);
    k_fuse2<<<NROWS/8, 256>>>(tgam, n3g, n3b);

    // ---- MLP ----
    hgemm_k<2,1><<<g1024, 256>>>(XAb, WB+W_M1, mb1, nullptr, Hb, NROWS, HIDN, CC);
    hgemm_k<3,0><<<g256, 256>>>(Hb, WB+W_M2, mb2, X, X, NROWS, CC, HIDN);

    // ---- downsample ----
    k_down<<<(BB*48*EE*CC/4)/256, 256>>>((float*)d_out);

    (void)in_sizes; (void)n_in; (void)out_size;
}

// round 13
// speedup vs baseline: 4.9859x; 1.1845x over previous
#include <cuda_runtime.h>
#include <cuda_bf16.h>
#include <math.h>

#define BB 8
#define TT 96
#define EE 96
#define CC 256
#define HH 8
#define DD 32
#define HIDN 1024
#define NROWS (BB*TT*EE)   /* 73728 */
#define EPSI 1e-5f

// ---------------- scratch (static device globals; no allocations) ----------------
__device__ float g_X [NROWS*CC];            // running residual x (fp32)
__device__ float g_XA[NROWS*CC];            // xs fp32 (residual add in fuse1)
__device__ __nv_bfloat16 g_XAb[NROWS*CC];   // LN outputs, bf16 (GEMM A)
__device__ __nv_bfloat16 g_QKVb[NROWS*768]; // fused QKV output
__device__ __nv_bfloat16 g_Ob [NROWS*CC];
__device__ __nv_bfloat16 g_Pb [NROWS*CC];
__device__ __nv_bfloat16 g_Hb [NROWS*HIDN];
// transposed bf16 weights: [N][K] each
#define W_SQ 0
#define W_SK 65536
#define W_SV 131072
#define W_SP 196608
#define W_TQ 262144
#define W_TK 327680
#define W_TV 393216
#define W_TP 458752
#define W_M1 524288
#define W_M2 786432
#define W_TOT 1048576
__device__ __nv_bfloat16 g_WB[W_TOT];

__device__ __forceinline__ float warpSum(float v) {
    #pragma unroll
    for (int o = 16; o; o >>= 1) v += __shfl_xor_sync(0xffffffffu, v, o);
    return v;
}
__device__ __forceinline__ unsigned packbf(float lo, float hi) {
    unsigned r;
    asm("cvt.rn.bf16x2.f32 %0, %1, %2;" : "=r"(r) : "f"(hi), "f"(lo));
    return r;
}
__device__ __forceinline__ float2 upack2(unsigned u) {
    return __bfloat1622float2(*(__nv_bfloat162*)&u);
}
__device__ __forceinline__ void unpack4(uint2 v, float* f) {
    __nv_bfloat162* h = (__nv_bfloat162*)&v;
    float2 a = __bfloat1622float2(h[0]); float2 b = __bfloat1622float2(h[1]);
    f[0]=a.x; f[1]=a.y; f[2]=b.x; f[3]=b.y;
}

#define MMA16816(c0,c1,c2,c3,a0,a1,a2,a3,b0,b1) \
    asm volatile( \
        "mma.sync.aligned.m16n8k16.row.col.f32.bf16.bf16.f32 " \
        "{%0,%1,%2,%3},{%4,%5,%6,%7},{%8,%9},{%0,%1,%2,%3};" \
        : "+f"(c0), "+f"(c1), "+f"(c2), "+f"(c3) \
        : "r"(a0), "r"(a1), "r"(a2), "r"(a3), "r"(b0), "r"(b1))

// ---------------- K0: weights -> transposed bf16 [N][K] ----------------
__global__ void k_wconv(const float* w0, const float* w1, const float* w2, const float* w3,
                        const float* w4, const float* w5, const float* w6, const float* w7,
                        const float* w8, const float* w9) {
    const float* srcs[10] = {w0,w1,w2,w3,w4,w5,w6,w7,w8,w9};
    const int offs[10] = {W_SQ,W_SK,W_SV,W_SP,W_TQ,W_TK,W_TV,W_TP,W_M1,W_M2};
    const int KsA[10]  = {256,256,256,256,256,256,256,256,256,1024};
    const int NsA[10]  = {256,256,256,256,256,256,256,256,1024,256};
    int gid = blockIdx.x * blockDim.x + threadIdx.x;   // 524288 threads
    int e0 = gid * 2;
    int seg;
    if (e0 < W_M1) seg = e0 >> 16;
    else if (e0 < W_M2) seg = 8;
    else seg = 9;
    int Ks = KsA[seg], Ns = NsA[seg];
    int rel2 = (e0 - offs[seg]) >> 1;
    int n = rel2 % Ns;
    int k0 = (rel2 / Ns) * 2;
    const float* s = srcs[seg];
    float lo = s[k0*Ns + n], hi = s[(k0+1)*Ns + n];
    *(unsigned*)(g_WB + offs[seg] + n*Ks + k0) = packbf(lo, hi);
}

// ---------------- K1: X = x ; XA = LN(x; n1) fp32 + bf16 ----------------
__global__ void k_ln1(const float* __restrict__ x,
                      const float* __restrict__ g, const float* __restrict__ b) {
    int warp = threadIdx.x >> 5, lane = threadIdx.x & 31;
    int row = blockIdx.x * 8 + warp;
    const float4* xr = (const float4*)(x + row*CC);
    float4 a0 = xr[lane], a1 = xr[lane+32];
    float4* Xr = (float4*)(g_X + row*CC);
    Xr[lane] = a0; Xr[lane+32] = a1;
    float f[8] = {a0.x,a0.y,a0.z,a0.w,a1.x,a1.y,a1.z,a1.w};
    float s = 0.f;
    #pragma unroll
    for (int j = 0; j < 8; j++) s += f[j];
    float m = warpSum(s) * (1.f/CC);
    float vs = 0.f;
    #pragma unroll
    for (int j = 0; j < 8; j++) { f[j] -= m; vs += f[j]*f[j]; }
    float r = rsqrtf(warpSum(vs) * (1.f/CC) + EPSI);
    float4 ga = ((const float4*)g)[lane], gb = ((const float4*)g)[lane+32];
    float4 ba = ((const float4*)b)[lane], bb = ((const float4*)b)[lane+32];
    float gf[8] = {ga.x,ga.y,ga.z,ga.w,gb.x,gb.y,gb.z,gb.w};
    float bf_[8] = {ba.x,ba.y,ba.z,ba.w,bb.x,bb.y,bb.z,bb.w};
    float o[8];
    #pragma unroll
    for (int j = 0; j < 8; j++) o[j] = f[j]*r*gf[j] + bf_[j];
    float4* Or = (float4*)(g_XA + row*CC);
    float4 o0 = {o[0],o[1],o[2],o[3]}, o1 = {o[4],o[5],o[6],o[7]};
    Or[lane] = o0; Or[lane+32] = o1;
    uint2* Ob2 = (uint2*)(g_XAb + row*CC);
    uint2 p0; p0.x = packbf(o[0],o[1]); p0.y = packbf(o[2],o[3]);
    uint2 p1; p1.x = packbf(o[4],o[5]); p1.y = packbf(o[6],o[7]);
    Ob2[lane] = p0; Ob2[lane+32] = p1;
}

// ---------------- bf16 GEMM 128x128x32; B pre-transposed [N][K] ----------------
#define T_STRIDE_U32 20   /* 40 bf16 per row (32 data + 8 pad) */

template<int EPI, int OUTBF>
__global__ void __launch_bounds__(256)
hgemm_k(const __nv_bfloat16* __restrict__ A, const __nv_bfloat16* __restrict__ Bt,
        const float* __restrict__ bias, const float* __restrict__ Res,
        void* __restrict__ Cout, int M, int N, int K) {
    __shared__ unsigned AsU[2][128 * T_STRIDE_U32];
    __shared__ unsigned BsU[2][128 * T_STRIDE_U32];

    int tid  = threadIdx.x;
    int bm   = blockIdx.y * 128, bn = blockIdx.x * 128;
    int lane = tid & 31, warp = tid >> 5;
    int wm   = (warp & 1) * 64, wn = (warp >> 1) * 32;
    int g    = lane >> 2, tig = lane & 3;

    int rowT = tid >> 2, colT = (tid & 3) * 8;   // 128x32 bf16 tile, 2 passes of 64 rows

    float acc[4][4][4];
    #pragma unroll
    for (int i = 0; i < 4; i++)
        #pragma unroll
        for (int j = 0; j < 4; j++)
            #pragma unroll
            for (int k = 0; k < 4; k++) acc[i][j][k] = 0.f;

    uint4 pa[2], pb[2];
    int kTiles = K >> 5;

    #pragma unroll
    for (int p = 0; p < 2; p++) {
        pa[p] = *(const uint4*)&A [(bm + rowT + p*64) * K + colT];
        pb[p] = *(const uint4*)&Bt[(bn + rowT + p*64) * K + colT];
    }
    #pragma unroll
    for (int p = 0; p < 2; p++) {
        unsigned* d = &AsU[0][(rowT + p*64) * T_STRIDE_U32 + (tid & 3) * 4];
        d[0] = pa[p].x; d[1] = pa[p].y; d[2] = pa[p].z; d[3] = pa[p].w;
        unsigned* e = &BsU[0][(rowT + p*64) * T_STRIDE_U32 + (tid & 3) * 4];
        e[0] = pb[p].x; e[1] = pb[p].y; e[2] = pb[p].z; e[3] = pb[p].w;
    }
    __syncthreads();

    for (int kt = 0; kt < kTiles; ++kt) {
        int buf = kt & 1;
        bool hasNext = (kt + 1 < kTiles);
        if (hasNext) {
            int kOff = (kt + 1) * 32;
            #pragma unroll
            for (int p = 0; p < 2; p++) {
                pa[p] = *(const uint4*)&A [(bm + rowT + p*64) * K + kOff + colT];
                pb[p] = *(const uint4*)&Bt[(bn + rowT + p*64) * K + kOff + colT];
            }
        }

        #pragma unroll
        for (int kh = 0; kh < 2; ++kh) {
            unsigned af[4][4];
            unsigned bfr[4][2];
            #pragma unroll
            for (int mi = 0; mi < 4; ++mi) {
                const unsigned* p = &AsU[buf][(wm + mi*16 + g) * T_STRIDE_U32 + kh*8 + tig];
                af[mi][0] = p[0];
                af[mi][1] = p[8 * T_STRIDE_U32];
                af[mi][2] = p[4];
                af[mi][3] = p[8 * T_STRIDE_U32 + 4];
            }
            #pragma unroll
            for (int ni = 0; ni < 4; ++ni) {
                const unsigned* q = &BsU[buf][(wn + ni*8 + g) * T_STRIDE_U32 + kh*8 + tig];
                bfr[ni][0] = q[0];
                bfr[ni][1] = q[4];
            }
            #pragma unroll
            for (int mi = 0; mi < 4; ++mi)
                #pragma unroll
                for (int ni = 0; ni < 4; ++ni)
                    MMA16816(acc[mi][ni][0], acc[mi][ni][1], acc[mi][ni][2], acc[mi][ni][3],
                             af[mi][0], af[mi][1], af[mi][2], af[mi][3],
                             bfr[ni][0], bfr[ni][1]);
        }

        if (hasNext) {
            int nb = buf ^ 1;
            #pragma unroll
            for (int p = 0; p < 2; p++) {
                unsigned* d = &AsU[nb][(rowT + p*64) * T_STRIDE_U32 + (tid & 3) * 4];
                d[0] = pa[p].x; d[1] = pa[p].y; d[2] = pa[p].z; d[3] = pa[p].w;
                unsigned* e = &BsU[nb][(rowT + p*64) * T_STRIDE_U32 + (tid & 3) * 4];
                e[0] = pb[p].x; e[1] = pb[p].y; e[2] = pb[p].z; e[3] = pb[p].w;
            }
            __syncthreads();
        }
    }

    #pragma unroll
    for (int mi = 0; mi < 4; ++mi) {
        int r0 = bm + wm + mi*16 + g;
        #pragma unroll
        for (int ni = 0; ni < 4; ++ni) {
            int c = bn + wn + ni*8 + tig*2;
            float v0 = acc[mi][ni][0], v1 = acc[mi][ni][1];
            float v2 = acc[mi][ni][2], v3 = acc[mi][ni][3];
            if (EPI >= 1) {
                float b0 = bias[c], b1 = bias[c+1];
                v0 += b0; v1 += b1; v2 += b0; v3 += b1;
            }
            if (EPI == 2) {
                v0 = 0.5f * v0 * (1.f + erff(v0 * 0.70710678118654752f));
                v1 = 0.5f * v1 * (1.f + erff(v1 * 0.70710678118654752f));
                v2 = 0.5f * v2 * (1.f + erff(v2 * 0.70710678118654752f));
                v3 = 0.5f * v3 * (1.f + erff(v3 * 0.70710678118654752f));
            }
            if (EPI == 3) {
                float2 ra = *(const float2*)&Res[r0 * N + c];
                float2 rb = *(const float2*)&Res[(r0 + 8) * N + c];
                v0 += ra.x; v1 += ra.y; v2 += rb.x; v3 += rb.y;
            }
            if (OUTBF) {
                unsigned* C32 = (unsigned*)Cout;
                C32[(r0 * N + c) >> 1]       = packbf(v0, v1);
                C32[((r0 + 8) * N + c) >> 1] = packbf(v2, v3);
            } else {
                float* Cf = (float*)Cout;
                float2 o0; o0.x = v0; o0.y = v1;
                float2 o1; o1.x = v2; o1.y = v3;
                *(float2*)&Cf[r0 * N + c]       = o0;
                *(float2*)&Cf[(r0 + 8) * N + c] = o1;
            }
        }
    }
}

// ---------------- attention via bf16 mma (reads fused QKV [NROWS][768]) --------
// compact smem: 41.7 KB -> 5 CTAs/SM
#define O_SQ   0                  /* 96 x 20 u32 */
#define O_SK   1920
#define O_SVT  3840               /* 32 x 49 u32 (V transposed, stride 98 bf16) */
#define O_SS   5408               /* 96 x 52 u32 (96 bf16 data + pad) */
#define O_COL  10400              /* 32 fp32 colsums */
#define ATTN_U32 10432
#define ATTN_SMEM (ATTN_U32 * 4)  /* 41728 bytes */

template<bool TEMPORAL>
__global__ void __launch_bounds__(256)
attn_mma(const __nv_bfloat16* __restrict__ QKV, __nv_bfloat16* __restrict__ O,
         const float* __restrict__ adj) {
    extern __shared__ unsigned su[];
    unsigned* sQ  = su + O_SQ;
    unsigned* sK  = su + O_SK;
    unsigned* sVt = su + O_SVT;
    unsigned* sS  = su + O_SS;
    float* sCol   = (float*)(su + O_COL);

    int tid = threadIdx.x, lane = tid & 31, warp = tid >> 5;
    int g = lane >> 2, tig = lane & 3;
    int h = blockIdx.y;
    int row0, qstride, ostride;
    if (TEMPORAL) {
        int b = blockIdx.x / EE, e = blockIdx.x % EE;
        row0 = b*TT*EE + e;
        qstride = EE*768; ostride = EE*CC;
    } else {
        row0 = blockIdx.x * EE;
        qstride = 768; ostride = CC;
    }
    int qbase = row0*768 + h*DD;
    int obase = row0*CC  + h*DD;
    const __nv_bfloat16* Qp = QKV + qbase;
    const __nv_bfloat16* Kp = QKV + qbase + 256;
    const __nv_bfloat16* Vp = QKV + qbase + 512;

    // Q, K: 96 rows x 32 bf16 = 4 uint4 per row
    for (int i = tid; i < 96*4; i += 256) {
        int s = i >> 2, part = i & 3;
        uint4 q4 = *(const uint4*)&Qp[s*qstride + part*8];
        uint4 k4 = *(const uint4*)&Kp[s*qstride + part*8];
        unsigned* dq = &sQ[s*20 + part*4];
        dq[0]=q4.x; dq[1]=q4.y; dq[2]=q4.z; dq[3]=q4.w;
        unsigned* dk = &sK[s*20 + part*4];
        dk[0]=k4.x; dk[1]=k4.y; dk[2]=k4.z; dk[3]=k4.w;
    }
    // V transposed (u16 copy)
    const unsigned short* Vs = (const unsigned short*)Vp;
    for (int i = tid; i < 96*32; i += 256) {
        int s = i >> 5, d = i & 31;
        ((unsigned short*)sVt)[d*98 + s] = Vs[s*qstride + d];
    }
    __syncthreads();

    // spatial: fp32 column sums of V from smem (lane = d, stride-49 rows: conflict-free)
    if (!TEMPORAL && tid < 32) {
        const unsigned* vrow = &sVt[tid*49];
        float cs = 0.f;
        #pragma unroll 8
        for (int s2 = 0; s2 < 48; s2++) {
            float2 v = upack2(vrow[s2]);
            cs += v.x + v.y;
        }
        sCol[tid] = cs;
    }

    // S = Q K^T : 72 tiles (6m x 12n)
    for (int t = warp; t < 72; t += 8) {
        int mi = t / 12, ni = t % 12;
        int m0 = mi*16, n0 = ni*8;
        float c0 = 0.f, c1 = 0.f, c2 = 0.f, c3 = 0.f;
        #pragma unroll
        for (int kh = 0; kh < 2; kh++) {
            unsigned a0 = sQ[(m0+g  )*20 + kh*8 + tig];
            unsigned a1 = sQ[(m0+g+8)*20 + kh*8 + tig];
            unsigned a2 = sQ[(m0+g  )*20 + kh*8 + tig + 4];
            unsigned a3 = sQ[(m0+g+8)*20 + kh*8 + tig + 4];
            unsigned b0 = sK[(n0+g)*20 + kh*8 + tig];
            unsigned b1 = sK[(n0+g)*20 + kh*8 + tig + 4];
            MMA16816(c0, c1, c2, c3, a0, a1, a2, a3, b0, b1);
        }
        int r0 = m0+g, r1 = m0+g+8, cc = n0 + tig*2;
        if (TEMPORAL) {
            const float sc = 0.17677669529663687f;  // 1/sqrt(32)
            sS[r0*52 + ni*4 + tig] = packbf(c0*sc, c1*sc);
            sS[r1*52 + ni*4 + tig] = packbf(c2*sc, c3*sc);
        } else {
            // u = s*adj*0.5 (adj direct from global: 36KB set, L2-resident)
            float2 a0 = *(const float2*)&adj[r0*96 + cc];
            float2 a1 = *(const float2*)&adj[r1*96 + cc];
            sS[r0*52 + ni*4 + tig] = packbf(c0*a0.x*0.5f, c1*a0.y*0.5f);
            sS[r1*52 + ni*4 + tig] = packbf(c2*a1.x*0.5f, c3*a1.y*0.5f);
        }
    }
    __syncthreads();

    if (TEMPORAL) {
        // in-place softmax on bf16 sS (fp32 math)
        for (int r = warp; r < 96; r += 8) {
            unsigned* row = &sS[r*52];
            float2 f0 = upack2(row[lane]);
            float f2 = -1e30f, f3 = -1e30f;
            if (lane < 16) {
                float2 t2 = upack2(row[32 + lane]);
                f2 = t2.x; f3 = t2.y;
            }
            float mx = fmaxf(fmaxf(f0.x, f0.y), fmaxf(f2, f3));
            #pragma unroll
            for (int o = 16; o; o >>= 1) mx = fmaxf(mx, __shfl_xor_sync(0xffffffffu, mx, o));
            float e0 = expf(f0.x - mx), e1 = expf(f0.y - mx);
            float e2 = (lane < 16) ? expf(f2 - mx) : 0.f;
            float e3 = (lane < 16) ? expf(f3 - mx) : 0.f;
            float s = warpSum(e0 + e1 + e2 + e3);
            float inv = 1.f / s;
            row[lane] = packbf(e0*inv, e1*inv);
            if (lane < 16) row[32 + lane] = packbf(e2*inv, e3*inv);
        }
        __syncthreads();
    }

    // O = S V : 24 tiles (6m x 4n), 3 per warp
    unsigned* O32 = (unsigned*)O;
    #pragma unroll
    for (int tt = 0; tt < 3; tt++) {
        int t = warp*3 + tt;
        int mi = t >> 2, ni = t & 3;
        int m0 = mi*16, n0 = ni*8;
        float c0 = 0.f, c1 = 0.f, c2 = 0.f, c3 = 0.f;
        #pragma unroll
        for (int ks = 0; ks < 6; ks++) {
            unsigned a0 = sS[(m0+g  )*52 + ks*8 + tig];
            unsigned a1 = sS[(m0+g+8)*52 + ks*8 + tig];
            unsigned a2 = sS[(m0+g  )*52 + ks*8 + tig + 4];
            unsigned a3 = sS[(m0+g+8)*52 + ks*8 + tig + 4];
            unsigned b0 = sVt[(n0+g)*49 + ks*8 + tig];
            unsigned b1 = sVt[(n0+g)*49 + ks*8 + tig + 4];
            MMA16816(c0, c1, c2, c3, a0, a1, a2, a3, b0, b1);
        }
        int cc = n0 + tig*2;
        if (!TEMPORAL) {
            float ca = 0.5f * sCol[cc], cb = 0.5f * sCol[cc+1];
            c0 += ca; c1 += cb; c2 += ca; c3 += cb;
        }
        O32[(obase + (m0+g  )*ostride + cc) >> 1] = packbf(c0, c1);
        O32[(obase + (m0+g+8)*ostride + cc) >> 1] = packbf(c2, c3);
    }
}

// ---------------- K5: p=LN(Pb;s_n); x += xs + s_gamma*p; XAb = LN(x; n2) --------
__global__ void k_fuse1(const float* __restrict__ sng, const float* __restrict__ snb,
                        const float* __restrict__ sgam,
                        const float* __restrict__ n2g, const float* __restrict__ n2b) {
    int warp = threadIdx.x >> 5, lane = threadIdx.x & 31;
    int row = blockIdx.x * 8 + warp;
    int bidx = row*CC;
    uint2 pv0 = ((const uint2*)(g_Pb+bidx))[lane], pv1 = ((const uint2*)(g_Pb+bidx))[lane+32];
    float pf[8];
    unpack4(pv0, pf); unpack4(pv1, pf+4);
    float s = 0.f;
    #pragma unroll
    for (int j = 0; j < 8; j++) s += pf[j];
    float m1 = warpSum(s) * (1.f/CC);
    float vs = 0.f;
    #pragma unroll
    for (int j = 0; j < 8; j++) { pf[j] -= m1; vs += pf[j]*pf[j]; }
    float r1 = rsqrtf(warpSum(vs) * (1.f/CC) + EPSI);
    float4 ga = ((const float4*)sng)[lane], gb = ((const float4*)sng)[lane+32];
    float4 ba = ((const float4*)snb)[lane], bb = ((const float4*)snb)[lane+32];
    float gf[8] = {ga.x,ga.y,ga.z,ga.w,gb.x,gb.y,gb.z,gb.w};
    float bf_[8] = {ba.x,ba.y,ba.z,ba.w,bb.x,bb.y,bb.z,bb.w};
    float gamma = sgam[0];
    float4 x0 = ((const float4*)(g_X+bidx))[lane],  x1 = ((const float4*)(g_X+bidx))[lane+32];
    float4 s0 = ((const float4*)(g_XA+bidx))[lane], s1 = ((const float4*)(g_XA+bidx))[lane+32];
    float xf[8] = {x0.x,x0.y,x0.z,x0.w,x1.x,x1.y,x1.z,x1.w};
    float sf[8] = {s0.x,s0.y,s0.z,s0.w,s1.x,s1.y,s1.z,s1.w};
    float xn[8];
    #pragma unroll
    for (int j = 0; j < 8; j++)
        xn[j] = xf[j] + sf[j] + gamma * (pf[j]*r1*gf[j] + bf_[j]);
    float4 w0 = {xn[0],xn[1],xn[2],xn[3]}, w1 = {xn[4],xn[5],xn[6],xn[7]};
    ((float4*)(g_X+bidx))[lane] = w0; ((float4*)(g_X+bidx))[lane+32] = w1;
    float s2 = 0.f;
    #pragma unroll
    for (int j = 0; j < 8; j++) s2 += xn[j];
    float m2 = warpSum(s2) * (1.f/CC);
    float vs2 = 0.f;
    #pragma unroll
    for (int j = 0; j < 8; j++) { xn[j] -= m2; vs2 += xn[j]*xn[j]; }
    float r2 = rsqrtf(warpSum(vs2) * (1.f/CC) + EPSI);
    float4 g2a = ((const float4*)n2g)[lane], g2b = ((const float4*)n2g)[lane+32];
    float4 b2a = ((const float4*)n2b)[lane], b2b = ((const float4*)n2b)[lane+32];
    float g2f[8] = {g2a.x,g2a.y,g2a.z,g2a.w,g2b.x,g2b.y,g2b.z,g2b.w};
    float b2f[8] = {b2a.x,b2a.y,b2a.z,b2a.w,b2b.x,b2b.y,b2b.z,b2b.w};
    float o[8];
    #pragma unroll
    for (int j = 0; j < 8; j++) o[j] = xn[j]*r2*g2f[j] + b2f[j];
    uint2* Ob2 = (uint2*)(g_XAb + bidx);
    uint2 q0; q0.x = packbf(o[0],o[1]); q0.y = packbf(o[2],o[3]);
    uint2 q1; q1.x = packbf(o[4],o[5]); q1.y = packbf(o[6],o[7]);
    Ob2[lane] = q0; Ob2[lane+32] = q1;
}

// ---------------- K9: x += t_gamma*Pb; XAb = LN(x; n3) ----------------
__global__ void k_fuse2(const float* __restrict__ tgam,
                        const float* __restrict__ n3g, const float* __restrict__ n3b) {
    int warp = threadIdx.x >> 5, lane = threadIdx.x & 31;
    int row = blockIdx.x * 8 + warp;
    int bidx = row*CC;
    float gamma = tgam[0];
    uint2 pv0 = ((const uint2*)(g_Pb+bidx))[lane], pv1 = ((const uint2*)(g_Pb+bidx))[lane+32];
    float pf[8];
    unpack4(pv0, pf); unpack4(pv1, pf+4);
    float4 x0 = ((const float4*)(g_X+bidx))[lane], x1 = ((const float4*)(g_X+bidx))[lane+32];
    float xn[8] = {x0.x + gamma*pf[0], x0.y + gamma*pf[1], x0.z + gamma*pf[2], x0.w + gamma*pf[3],
                   x1.x + gamma*pf[4], x1.y + gamma*pf[5], x1.z + gamma*pf[6], x1.w + gamma*pf[7]};
    float4 w0 = {xn[0],xn[1],xn[2],xn[3]}, w1 = {xn[4],xn[5],xn[6],xn[7]};
    ((float4*)(g_X+bidx))[lane] = w0; ((float4*)(g_X+bidx))[lane+32] = w1;
    float s = 0.f;
    #pragma unroll
    for (int j = 0; j < 8; j++) s += xn[j];
    float m = warpSum(s) * (1.f/CC);
    float vs = 0.f;
    #pragma unroll
    for (int j = 0; j < 8; j++) { xn[j] -= m; vs += xn[j]*xn[j]; }
    float r = rsqrtf(warpSum(vs) * (1.f/CC) + EPSI);
    float4 ga = ((const float4*)n3g)[lane], gb = ((const float4*)n3g)[lane+32];
    float4 ba = ((const float4*)n3b)[lane], bb = ((const float4*)n3b)[lane+32];
    float gf[8] = {ga.x,ga.y,ga.z,ga.w,gb.x,gb.y,gb.z,gb.w};
    float bf_[8] = {ba.x,ba.y,ba.z,ba.w,bb.x,bb.y,bb.z,bb.w};
    float o[8];
    #pragma unroll
    for (int j = 0; j < 8; j++) o[j] = xn[j]*r*gf[j] + bf_[j];
    uint2* Ob2 = (uint2*)(g_XAb + bidx);
    uint2 q0; q0.x = packbf(o[0],o[1]); q0.y = packbf(o[2],o[3]);
    uint2 q1; q1.x = packbf(o[4],o[5]); q1.y = packbf(o[6],o[7]);
    Ob2[lane] = q0; Ob2[lane+32] = q1;
}

// ---------------- K12: temporal downsample ----------------
__global__ void k_down(float* __restrict__ out) {
    int i = blockIdx.x * blockDim.x + threadIdx.x;
    const float4* X4 = (const float4*)g_X;
    const int EC4 = EE*CC/4;
    int ec = i % EC4;
    int rest = i / EC4;
    int t2 = rest % 48;
    int b  = rest / 48;
    int in0 = (b*96 + 2*t2) * EC4 + ec;
    float4 a = X4[in0], c = X4[in0 + EC4];
    float4 o;
    o.x = 0.5f*(a.x + c.x); o.y = 0.5f*(a.y + c.y);
    o.z = 0.5f*(a.z + c.z); o.w = 0.5f*(a.w + c.w);
    ((float4*)out)[i] = o;
}

// ---------------- host ----------------
extern "C" void kernel_launch(void* const* d_in, const int* in_sizes, int n_in,
                              void* d_out, int out_size) {
    const float* x    = (const float*)d_in[0];
    const float* adj  = (const float*)d_in[1];
    const float* n1g  = (const float*)d_in[2];
    const float* n1b  = (const float*)d_in[3];
    const float* swq  = (const float*)d_in[4];
    const float* swk  = (const float*)d_in[5];
    const float* swv  = (const float*)d_in[6];
    const float* swp  = (const float*)d_in[7];
    const float* sbp  = (const float*)d_in[8];
    const float* sng  = (const float*)d_in[9];
    const float* snb  = (const float*)d_in[10];
    const float* sgam = (const float*)d_in[11];
    const float* n2g  = (const float*)d_in[12];
    const float* n2b  = (const float*)d_in[13];
    const float* twq  = (const float*)d_in[14];
    const float* twk  = (const float*)d_in[15];
    const float* twv  = (const float*)d_in[16];
    const float* twp  = (const float*)d_in[17];
    const float* tbp  = (const float*)d_in[18];
    const float* tgam = (const float*)d_in[19];
    const float* n3g  = (const float*)d_in[20];
    const float* n3b  = (const float*)d_in[21];
    const float* mw1  = (const float*)d_in[22];
    const float* mb1  = (const float*)d_in[23];
    const float* mw2  = (const float*)d_in[24];
    const float* mb2  = (const float*)d_in[25];

    float *X;
    __nv_bfloat16 *XAb, *QKVb, *Ob, *Pb, *Hb, *WB;
    cudaGetSymbolAddress((void**)&X,    g_X);
    cudaGetSymbolAddress((void**)&XAb,  g_XAb);
    cudaGetSymbolAddress((void**)&QKVb, g_QKVb);
    cudaGetSymbolAddress((void**)&Ob,   g_Ob);
    cudaGetSymbolAddress((void**)&Pb,   g_Pb);
    cudaGetSymbolAddress((void**)&Hb,   g_Hb);
    cudaGetSymbolAddress((void**)&WB,   g_WB);

    cudaFuncSetAttribute(attn_mma<false>, cudaFuncAttributeMaxDynamicSharedMemorySize, ATTN_SMEM);
    cudaFuncSetAttribute(attn_mma<true>,  cudaFuncAttributeMaxDynamicSharedMemorySize, ATTN_SMEM);

    dim3 g256(2, NROWS/128);     // N=256
    dim3 g768(6, NROWS/128);     // N=768 fused QKV
    dim3 g1024(8, NROWS/128);    // N=1024

    k_wconv<<<2048, 256>>>(swq, swk, swv, swp, twq, twk, twv, twp, mw1, mw2);

    // ---- spatial block ----
    k_ln1<<<NROWS/8, 256>>>(x, n1g, n1b);
    hgemm_k<0,1><<<g768, 256>>>(XAb, WB+W_SQ, nullptr, nullptr, QKVb, NROWS, 768, CC);
    attn_mma<false><<<dim3(BB*TT, HH), 256, ATTN_SMEM>>>(QKVb, Ob, adj);
    hgemm_k<1,1><<<g256, 256>>>(Ob, WB+W_SP, sbp, nullptr, Pb, NROWS, CC, CC);
    k_fuse1<<<NROWS/8, 256>>>(sng, snb, sgam, n2g, n2b);

    // ---- temporal block ----
    hgemm_k<0,1><<<g768, 256>>>(XAb, WB+W_TQ, nullptr, nullptr, QKVb, NROWS, 768, CC);
    attn_mma<true><<<dim3(BB*EE, HH), 256, ATTN_SMEM>>>(QKVb, Ob, nullptr);
    hgemm_k<1,1><<<g256, 256>>>(Ob, WB+W_TP, tbp, nullptr, Pb, NROWS, CC, CC);
    k_fuse2<<<NROWS/8, 256>>>(tgam, n3g, n3b);

    // ---- MLP ----
    hgemm_k<2,1><<<g1024, 256>>>(XAb, WB+W_M1, mb1, nullptr, Hb, NROWS, HIDN, CC);
    hgemm_k<3,0><<<g256, 256>>>(Hb, WB+W_M2, mb2, X, X, NROWS, CC, HIDN);

    // ---- downsample ----
    k_down<<<(BB*48*EE*CC/4)/256, 256>>>((float*)d_out);

    (void)in_sizes; (void)n_in; (void)out_size;
}

// round 14
// speedup vs baseline: 5.0863x; 1.0201x over previous
#include <cuda_runtime.h>
#include <cuda_bf16.h>
#include <math.h>

#define BB 8
#define TT 96
#define EE 96
#define CC 256
#define HH 8
#define DD 32
#define HIDN 1024
#define NROWS (BB*TT*EE)   /* 73728 */
#define EPSI 1e-5f

// ---------------- scratch (static device globals; no allocations) ----------------
__device__ float g_X [NROWS*CC];            // running residual x (fp32)
__device__ float g_XA[NROWS*CC];            // xs fp32 (residual add in fuse1)
__device__ __nv_bfloat16 g_XAb[NROWS*CC];   // LN outputs, bf16 (GEMM A)
__device__ __nv_bfloat16 g_QKVb[NROWS*768]; // fused QKV output
__device__ __nv_bfloat16 g_Ob [NROWS*CC];
__device__ __nv_bfloat16 g_Pb [NROWS*CC];
__device__ __nv_bfloat16 g_Hb [NROWS*HIDN];
// transposed bf16 weights: [N][K] each
#define W_SQ 0
#define W_SK 65536
#define W_SV 131072
#define W_SP 196608
#define W_TQ 262144
#define W_TK 327680
#define W_TV 393216
#define W_TP 458752
#define W_M1 524288
#define W_M2 786432
#define W_TOT 1048576
__device__ __nv_bfloat16 g_WB[W_TOT];

__device__ __forceinline__ float warpSum(float v) {
    #pragma unroll
    for (int o = 16; o; o >>= 1) v += __shfl_xor_sync(0xffffffffu, v, o);
    return v;
}
__device__ __forceinline__ unsigned packbf(float lo, float hi) {
    unsigned r;
    asm("cvt.rn.bf16x2.f32 %0, %1, %2;" : "=r"(r) : "f"(hi), "f"(lo));
    return r;
}
__device__ __forceinline__ float2 upack2(unsigned u) {
    return __bfloat1622float2(*(__nv_bfloat162*)&u);
}
__device__ __forceinline__ void unpack4(uint2 v, float* f) {
    __nv_bfloat162* h = (__nv_bfloat162*)&v;
    float2 a = __bfloat1622float2(h[0]); float2 b = __bfloat1622float2(h[1]);
    f[0]=a.x; f[1]=a.y; f[2]=b.x; f[3]=b.y;
}

#define MMA16816(c0,c1,c2,c3,a0,a1,a2,a3,b0,b1) \
    asm volatile( \
        "mma.sync.aligned.m16n8k16.row.col.f32.bf16.bf16.f32 " \
        "{%0,%1,%2,%3},{%4,%5,%6,%7},{%8,%9},{%0,%1,%2,%3};" \
        : "+f"(c0), "+f"(c1), "+f"(c2), "+f"(c3) \
        : "r"(a0), "r"(a1), "r"(a2), "r"(a3), "r"(b0), "r"(b1))

// ---------------- K0: weights -> transposed bf16 [N][K] ----------------
__global__ void k_wconv(const float* w0, const float* w1, const float* w2, const float* w3,
                        const float* w4, const float* w5, const float* w6, const float* w7,
                        const float* w8, const float* w9) {
    const float* srcs[10] = {w0,w1,w2,w3,w4,w5,w6,w7,w8,w9};
    const int offs[10] = {W_SQ,W_SK,W_SV,W_SP,W_TQ,W_TK,W_TV,W_TP,W_M1,W_M2};
    const int KsA[10]  = {256,256,256,256,256,256,256,256,256,1024};
    const int NsA[10]  = {256,256,256,256,256,256,256,256,1024,256};
    int gid = blockIdx.x * blockDim.x + threadIdx.x;   // 524288 threads
    int e0 = gid * 2;
    int seg;
    if (e0 < W_M1) seg = e0 >> 16;
    else if (e0 < W_M2) seg = 8;
    else seg = 9;
    int Ks = KsA[seg], Ns = NsA[seg];
    int rel2 = (e0 - offs[seg]) >> 1;
    int n = rel2 % Ns;
    int k0 = (rel2 / Ns) * 2;
    const float* s = srcs[seg];
    float lo = s[k0*Ns + n], hi = s[(k0+1)*Ns + n];
    *(unsigned*)(g_WB + offs[seg] + n*Ks + k0) = packbf(lo, hi);
}

// ---------------- K1: X = x ; XA = LN(x; n1) fp32 + bf16 ----------------
__global__ void k_ln1(const float* __restrict__ x,
                      const float* __restrict__ g, const float* __restrict__ b) {
    int warp = threadIdx.x >> 5, lane = threadIdx.x & 31;
    int row = blockIdx.x * 8 + warp;
    const float4* xr = (const float4*)(x + row*CC);
    float4 a0 = xr[lane], a1 = xr[lane+32];
    float4* Xr = (float4*)(g_X + row*CC);
    Xr[lane] = a0; Xr[lane+32] = a1;
    float f[8] = {a0.x,a0.y,a0.z,a0.w,a1.x,a1.y,a1.z,a1.w};
    float s = 0.f;
    #pragma unroll
    for (int j = 0; j < 8; j++) s += f[j];
    float m = warpSum(s) * (1.f/CC);
    float vs = 0.f;
    #pragma unroll
    for (int j = 0; j < 8; j++) { f[j] -= m; vs += f[j]*f[j]; }
    float r = rsqrtf(warpSum(vs) * (1.f/CC) + EPSI);
    float4 ga = ((const float4*)g)[lane], gb = ((const float4*)g)[lane+32];
    float4 ba = ((const float4*)b)[lane], bb = ((const float4*)b)[lane+32];
    float gf[8] = {ga.x,ga.y,ga.z,ga.w,gb.x,gb.y,gb.z,gb.w};
    float bf_[8] = {ba.x,ba.y,ba.z,ba.w,bb.x,bb.y,bb.z,bb.w};
    float o[8];
    #pragma unroll
    for (int j = 0; j < 8; j++) o[j] = f[j]*r*gf[j] + bf_[j];
    float4* Or = (float4*)(g_XA + row*CC);
    float4 o0 = {o[0],o[1],o[2],o[3]}, o1 = {o[4],o[5],o[6],o[7]};
    Or[lane] = o0; Or[lane+32] = o1;
    uint2* Ob2 = (uint2*)(g_XAb + row*CC);
    uint2 p0; p0.x = packbf(o[0],o[1]); p0.y = packbf(o[2],o[3]);
    uint2 p1; p1.x = packbf(o[4],o[5]); p1.y = packbf(o[6],o[7]);
    Ob2[lane] = p0; Ob2[lane+32] = p1;
}

// ---------------- bf16 GEMM 128x128x32; B pre-transposed [N][K] ----------------
#define T_STRIDE_U32 20   /* 40 bf16 per row (32 data + 8 pad) */

template<int EPI, int OUTBF>
__global__ void __launch_bounds__(256)
hgemm_k(const __nv_bfloat16* __restrict__ A, const __nv_bfloat16* __restrict__ Bt,
        const float* __restrict__ bias, const float* __restrict__ Res,
        void* __restrict__ Cout, int M, int N, int K) {
    __shared__ unsigned AsU[2][128 * T_STRIDE_U32];
    __shared__ unsigned BsU[2][128 * T_STRIDE_U32];

    int tid  = threadIdx.x;
    int bm   = blockIdx.y * 128, bn = blockIdx.x * 128;
    int lane = tid & 31, warp = tid >> 5;
    int wm   = (warp & 1) * 64, wn = (warp >> 1) * 32;
    int g    = lane >> 2, tig = lane & 3;

    int rowT = tid >> 2, colT = (tid & 3) * 8;   // 128x32 bf16 tile, 2 passes of 64 rows

    float acc[4][4][4];
    #pragma unroll
    for (int i = 0; i < 4; i++)
        #pragma unroll
        for (int j = 0; j < 4; j++)
            #pragma unroll
            for (int k = 0; k < 4; k++) acc[i][j][k] = 0.f;

    uint4 pa[2], pb[2];
    int kTiles = K >> 5;

    #pragma unroll
    for (int p = 0; p < 2; p++) {
        pa[p] = *(const uint4*)&A [(bm + rowT + p*64) * K + colT];
        pb[p] = *(const uint4*)&Bt[(bn + rowT + p*64) * K + colT];
    }
    #pragma unroll
    for (int p = 0; p < 2; p++) {
        unsigned* d = &AsU[0][(rowT + p*64) * T_STRIDE_U32 + (tid & 3) * 4];
        d[0] = pa[p].x; d[1] = pa[p].y; d[2] = pa[p].z; d[3] = pa[p].w;
        unsigned* e = &BsU[0][(rowT + p*64) * T_STRIDE_U32 + (tid & 3) * 4];
        e[0] = pb[p].x; e[1] = pb[p].y; e[2] = pb[p].z; e[3] = pb[p].w;
    }
    __syncthreads();

    for (int kt = 0; kt < kTiles; ++kt) {
        int buf = kt & 1;
        bool hasNext = (kt + 1 < kTiles);
        if (hasNext) {
            int kOff = (kt + 1) * 32;
            #pragma unroll
            for (int p = 0; p < 2; p++) {
                pa[p] = *(const uint4*)&A [(bm + rowT + p*64) * K + kOff + colT];
                pb[p] = *(const uint4*)&Bt[(bn + rowT + p*64) * K + kOff + colT];
            }
        }

        #pragma unroll
        for (int kh = 0; kh < 2; ++kh) {
            unsigned af[4][4];
            unsigned bfr[4][2];
            #pragma unroll
            for (int mi = 0; mi < 4; ++mi) {
                const unsigned* p = &AsU[buf][(wm + mi*16 + g) * T_STRIDE_U32 + kh*8 + tig];
                af[mi][0] = p[0];
                af[mi][1] = p[8 * T_STRIDE_U32];
                af[mi][2] = p[4];
                af[mi][3] = p[8 * T_STRIDE_U32 + 4];
            }
            #pragma unroll
            for (int ni = 0; ni < 4; ++ni) {
                const unsigned* q = &BsU[buf][(wn + ni*8 + g) * T_STRIDE_U32 + kh*8 + tig];
                bfr[ni][0] = q[0];
                bfr[ni][1] = q[4];
            }
            #pragma unroll
            for (int mi = 0; mi < 4; ++mi)
                #pragma unroll
                for (int ni = 0; ni < 4; ++ni)
                    MMA16816(acc[mi][ni][0], acc[mi][ni][1], acc[mi][ni][2], acc[mi][ni][3],
                             af[mi][0], af[mi][1], af[mi][2], af[mi][3],
                             bfr[ni][0], bfr[ni][1]);
        }

        if (hasNext) {
            int nb = buf ^ 1;
            #pragma unroll
            for (int p = 0; p < 2; p++) {
                unsigned* d = &AsU[nb][(rowT + p*64) * T_STRIDE_U32 + (tid & 3) * 4];
                d[0] = pa[p].x; d[1] = pa[p].y; d[2] = pa[p].z; d[3] = pa[p].w;
                unsigned* e = &BsU[nb][(rowT + p*64) * T_STRIDE_U32 + (tid & 3) * 4];
                e[0] = pb[p].x; e[1] = pb[p].y; e[2] = pb[p].z; e[3] = pb[p].w;
            }
            __syncthreads();
        }
    }

    #pragma unroll
    for (int mi = 0; mi < 4; ++mi) {
        int r0 = bm + wm + mi*16 + g;
        #pragma unroll
        for (int ni = 0; ni < 4; ++ni) {
            int c = bn + wn + ni*8 + tig*2;
            float v0 = acc[mi][ni][0], v1 = acc[mi][ni][1];
            float v2 = acc[mi][ni][2], v3 = acc[mi][ni][3];
            if (EPI >= 1) {
                float b0 = bias[c], b1 = bias[c+1];
                v0 += b0; v1 += b1; v2 += b0; v3 += b1;
            }
            if (EPI == 2) {
                v0 = 0.5f * v0 * (1.f + erff(v0 * 0.70710678118654752f));
                v1 = 0.5f * v1 * (1.f + erff(v1 * 0.70710678118654752f));
                v2 = 0.5f * v2 * (1.f + erff(v2 * 0.70710678118654752f));
                v3 = 0.5f * v3 * (1.f + erff(v3 * 0.70710678118654752f));
            }
            if (EPI == 3) {
                float2 ra = *(const float2*)&Res[r0 * N + c];
                float2 rb = *(const float2*)&Res[(r0 + 8) * N + c];
                v0 += ra.x; v1 += ra.y; v2 += rb.x; v3 += rb.y;
            }
            if (OUTBF) {
                unsigned* C32 = (unsigned*)Cout;
                C32[(r0 * N + c) >> 1]       = packbf(v0, v1);
                C32[((r0 + 8) * N + c) >> 1] = packbf(v2, v3);
            } else {
                float* Cf = (float*)Cout;
                float2 o0; o0.x = v0; o0.y = v1;
                float2 o1; o1.x = v2; o1.y = v3;
                *(float2*)&Cf[r0 * N + c]       = o0;
                *(float2*)&Cf[(r0 + 8) * N + c] = o1;
            }
        }
    }
}

// ---------------- attention via bf16 mma (reads fused QKV [NROWS][768]) --------
// compact smem 41.7 KB (5 CTAs/SM); warp-strip mapping with fragment reuse
#define O_SQ   0                  /* 96 x 20 u32 */
#define O_SK   1920
#define O_SVT  3840               /* 32 x 49 u32 (V transposed, stride 98 bf16) */
#define O_SS   5408               /* 96 x 52 u32 (96 bf16 data + pad) */
#define O_COL  10400              /* 32 fp32 colsums */
#define ATTN_U32 10432
#define ATTN_SMEM (ATTN_U32 * 4)  /* 41728 bytes */

template<bool TEMPORAL>
__global__ void __launch_bounds__(256)
attn_mma(const __nv_bfloat16* __restrict__ QKV, __nv_bfloat16* __restrict__ O,
         const float* __restrict__ adj) {
    extern __shared__ unsigned su[];
    unsigned* sQ  = su + O_SQ;
    unsigned* sK  = su + O_SK;
    unsigned* sVt = su + O_SVT;
    unsigned* sS  = su + O_SS;
    float* sCol   = (float*)(su + O_COL);

    int tid = threadIdx.x, lane = tid & 31, warp = tid >> 5;
    int g = lane >> 2, tig = lane & 3;
    int h = blockIdx.y;
    int row0, qstride, ostride;
    if (TEMPORAL) {
        int b = blockIdx.x / EE, e = blockIdx.x % EE;
        row0 = b*TT*EE + e;
        qstride = EE*768; ostride = EE*CC;
    } else {
        row0 = blockIdx.x * EE;
        qstride = 768; ostride = CC;
    }
    int qbase = row0*768 + h*DD;
    int obase = row0*CC  + h*DD;
    const __nv_bfloat16* Qp = QKV + qbase;
    const __nv_bfloat16* Kp = QKV + qbase + 256;
    const __nv_bfloat16* Vp = QKV + qbase + 512;

    // Q, K: 96 rows x 32 bf16 = 4 uint4 per row
    for (int i = tid; i < 96*4; i += 256) {
        int s = i >> 2, part = i & 3;
        uint4 q4 = *(const uint4*)&Qp[s*qstride + part*8];
        uint4 k4 = *(const uint4*)&Kp[s*qstride + part*8];
        unsigned* dq = &sQ[s*20 + part*4];
        dq[0]=q4.x; dq[1]=q4.y; dq[2]=q4.z; dq[3]=q4.w;
        unsigned* dk = &sK[s*20 + part*4];
        dk[0]=k4.x; dk[1]=k4.y; dk[2]=k4.z; dk[3]=k4.w;
    }
    // V transposed (u16 copy)
    const unsigned short* Vs = (const unsigned short*)Vp;
    for (int i = tid; i < 96*32; i += 256) {
        int s = i >> 5, d = i & 31;
        ((unsigned short*)sVt)[d*98 + s] = Vs[s*qstride + d];
    }
    __syncthreads();

    // spatial: fp32 column sums of V from smem (lane = d, stride-49 rows: conflict-free)
    if (!TEMPORAL && tid < 32) {
        const unsigned* vrow = &sVt[tid*49];
        float cs = 0.f;
        #pragma unroll 8
        for (int s2 = 0; s2 < 48; s2++) {
            float2 v = upack2(vrow[s2]);
            cs += v.x + v.y;
        }
        sCol[tid] = cs;
    }

    // S = Q K^T : warp w<6 owns full m16 x n96 strip; A fragments loaded ONCE
    if (warp < 6) {
        int m0 = warp * 16;
        int r0 = m0 + g, r1 = m0 + g + 8;
        unsigned aS[2][4];
        #pragma unroll
        for (int kh = 0; kh < 2; kh++) {
            const unsigned* p0 = &sQ[r0*20 + kh*8 + tig];
            const unsigned* p1 = &sQ[r1*20 + kh*8 + tig];
            aS[kh][0] = p0[0]; aS[kh][1] = p1[0];
            aS[kh][2] = p0[4]; aS[kh][3] = p1[4];
        }
        #pragma unroll
        for (int ni = 0; ni < 12; ni++) {
            int n0 = ni*8;
            float c0 = 0.f, c1 = 0.f, c2 = 0.f, c3 = 0.f;
            #pragma unroll
            for (int kh = 0; kh < 2; kh++) {
                unsigned b0 = sK[(n0+g)*20 + kh*8 + tig];
                unsigned b1 = sK[(n0+g)*20 + kh*8 + tig + 4];
                MMA16816(c0, c1, c2, c3,
                         aS[kh][0], aS[kh][1], aS[kh][2], aS[kh][3], b0, b1);
            }
            int cc = n0 + tig*2;
            if (TEMPORAL) {
                const float sc = 0.17677669529663687f;  // 1/sqrt(32)
                sS[r0*52 + ni*4 + tig] = packbf(c0*sc, c1*sc);
                sS[r1*52 + ni*4 + tig] = packbf(c2*sc, c3*sc);
            } else {
                float2 a0 = *(const float2*)&adj[r0*96 + cc];
                float2 a1 = *(const float2*)&adj[r1*96 + cc];
                sS[r0*52 + ni*4 + tig] = packbf(c0*a0.x*0.5f, c1*a0.y*0.5f);
                sS[r1*52 + ni*4 + tig] = packbf(c2*a1.x*0.5f, c3*a1.y*0.5f);
            }
        }
    }
    __syncthreads();

    if (TEMPORAL) {
        // in-place softmax on bf16 sS (fp32 math)
        for (int r = warp; r < 96; r += 8) {
            unsigned* row = &sS[r*52];
            float2 f0 = upack2(row[lane]);
            float f2 = -1e30f, f3 = -1e30f;
            if (lane < 16) {
                float2 t2 = upack2(row[32 + lane]);
                f2 = t2.x; f3 = t2.y;
            }
            float mx = fmaxf(fmaxf(f0.x, f0.y), fmaxf(f2, f3));
            #pragma unroll
            for (int o = 16; o; o >>= 1) mx = fmaxf(mx, __shfl_xor_sync(0xffffffffu, mx, o));
            float e0 = expf(f0.x - mx), e1 = expf(f0.y - mx);
            float e2 = (lane < 16) ? expf(f2 - mx) : 0.f;
            float e3 = (lane < 16) ? expf(f3 - mx) : 0.f;
            float s = warpSum(e0 + e1 + e2 + e3);
            float inv = 1.f / s;
            row[lane] = packbf(e0*inv, e1*inv);
            if (lane < 16) row[32 + lane] = packbf(e2*inv, e3*inv);
        }
        __syncthreads();
    }

    // O = S V : warp w<6 owns m16 x n32; ks-outer, 4 accumulators, A loaded once/ks
    unsigned* O32 = (unsigned*)O;
    if (warp < 6) {
        int m0 = warp * 16;
        int r0 = m0 + g, r1 = m0 + g + 8;
        float c[4][4];
        #pragma unroll
        for (int ni = 0; ni < 4; ni++)
            #pragma unroll
            for (int j = 0; j < 4; j++) c[ni][j] = 0.f;
        #pragma unroll
        for (int ks = 0; ks < 6; ks++) {
            unsigned a0 = sS[r0*52 + ks*8 + tig];
            unsigned a1 = sS[r1*52 + ks*8 + tig];
            unsigned a2 = sS[r0*52 + ks*8 + tig + 4];
            unsigned a3 = sS[r1*52 + ks*8 + tig + 4];
            #pragma unroll
            for (int ni = 0; ni < 4; ni++) {
                unsigned b0 = sVt[(ni*8+g)*49 + ks*8 + tig];
                unsigned b1 = sVt[(ni*8+g)*49 + ks*8 + tig + 4];
                MMA16816(c[ni][0], c[ni][1], c[ni][2], c[ni][3], a0, a1, a2, a3, b0, b1);
            }
        }
        #pragma unroll
        for (int ni = 0; ni < 4; ni++) {
            int cc = ni*8 + tig*2;
            float v0 = c[ni][0], v1 = c[ni][1], v2 = c[ni][2], v3 = c[ni][3];
            if (!TEMPORAL) {
                float ca = 0.5f * sCol[cc], cb = 0.5f * sCol[cc+1];
                v0 += ca; v1 += cb; v2 += ca; v3 += cb;
            }
            O32[(obase + r0*ostride + cc) >> 1] = packbf(v0, v1);
            O32[(obase + r1*ostride + cc) >> 1] = packbf(v2, v3);
        }
    }
}

// ---------------- K5: p=LN(Pb;s_n); x += xs + s_gamma*p; XAb = LN(x; n2) --------
__global__ void k_fuse1(const float* __restrict__ sng, const float* __restrict__ snb,
                        const float* __restrict__ sgam,
                        const float* __restrict__ n2g, const float* __restrict__ n2b) {
    int warp = threadIdx.x >> 5, lane = threadIdx.x & 31;
    int row = blockIdx.x * 8 + warp;
    int bidx = row*CC;
    uint2 pv0 = ((const uint2*)(g_Pb+bidx))[lane], pv1 = ((const uint2*)(g_Pb+bidx))[lane+32];
    float pf[8];
    unpack4(pv0, pf); unpack4(pv1, pf+4);
    float s = 0.f;
    #pragma unroll
    for (int j = 0; j < 8; j++) s += pf[j];
    float m1 = warpSum(s) * (1.f/CC);
    float vs = 0.f;
    #pragma unroll
    for (int j = 0; j < 8; j++) { pf[j] -= m1; vs += pf[j]*pf[j]; }
    float r1 = rsqrtf(warpSum(vs) * (1.f/CC) + EPSI);
    float4 ga = ((const float4*)sng)[lane], gb = ((const float4*)sng)[lane+32];
    float4 ba = ((const float4*)snb)[lane], bb = ((const float4*)snb)[lane+32];
    float gf[8] = {ga.x,ga.y,ga.z,ga.w,gb.x,gb.y,gb.z,gb.w};
    float bf_[8] = {ba.x,ba.y,ba.z,ba.w,bb.x,bb.y,bb.z,bb.w};
    float gamma = sgam[0];
    float4 x0 = ((const float4*)(g_X+bidx))[lane],  x1 = ((const float4*)(g_X+bidx))[lane+32];
    float4 s0 = ((const float4*)(g_XA+bidx))[lane], s1 = ((const float4*)(g_XA+bidx))[lane+32];
    float xf[8] = {x0.x,x0.y,x0.z,x0.w,x1.x,x1.y,x1.z,x1.w};
    float sf[8] = {s0.x,s0.y,s0.z,s0.w,s1.x,s1.y,s1.z,s1.w};
    float xn[8];
    #pragma unroll
    for (int j = 0; j < 8; j++)
        xn[j] = xf[j] + sf[j] + gamma * (pf[j]*r1*gf[j] + bf_[j]);
    float4 w0 = {xn[0],xn[1],xn[2],xn[3]}, w1 = {xn[4],xn[5],xn[6],xn[7]};
    ((float4*)(g_X+bidx))[lane] = w0; ((float4*)(g_X+bidx))[lane+32] = w1;
    float s2 = 0.f;
    #pragma unroll
    for (int j = 0; j < 8; j++) s2 += xn[j];
    float m2 = warpSum(s2) * (1.f/CC);
    float vs2 = 0.f;
    #pragma unroll
    for (int j = 0; j < 8; j++) { xn[j] -= m2; vs2 += xn[j]*xn[j]; }
    float r2 = rsqrtf(warpSum(vs2) * (1.f/CC) + EPSI);
    float4 g2a = ((const float4*)n2g)[lane], g2b = ((const float4*)n2g)[lane+32];
    float4 b2a = ((const float4*)n2b)[lane], b2b = ((const float4*)n2b)[lane+32];
    float g2f[8] = {g2a.x,g2a.y,g2a.z,g2a.w,g2b.x,g2b.y,g2b.z,g2b.w};
    float b2f[8] = {b2a.x,b2a.y,b2a.z,b2a.w,b2b.x,b2b.y,b2b.z,b2b.w};
    float o[8];
    #pragma unroll
    for (int j = 0; j < 8; j++) o[j] = xn[j]*r2*g2f[j] + b2f[j];
    uint2* Ob2 = (uint2*)(g_XAb + bidx);
    uint2 q0; q0.x = packbf(o[0],o[1]); q0.y = packbf(o[2],o[3]);
    uint2 q1; q1.x = packbf(o[4],o[5]); q1.y = packbf(o[6],o[7]);
    Ob2[lane] = q0; Ob2[lane+32] = q1;
}

// ---------------- K9: x += t_gamma*Pb; XAb = LN(x; n3) ----------------
__global__ void k_fuse2(const float* __restrict__ tgam,
                        const float* __restrict__ n3g, const float* __restrict__ n3b) {
    int warp = threadIdx.x >> 5, lane = threadIdx.x & 31;
    int row = blockIdx.x * 8 + warp;
    int bidx = row*CC;
    float gamma = tgam[0];
    uint2 pv0 = ((const uint2*)(g_Pb+bidx))[lane], pv1 = ((const uint2*)(g_Pb+bidx))[lane+32];
    float pf[8];
    unpack4(pv0, pf); unpack4(pv1, pf+4);
    float4 x0 = ((const float4*)(g_X+bidx))[lane], x1 = ((const float4*)(g_X+bidx))[lane+32];
    float xn[8] = {x0.x + gamma*pf[0], x0.y + gamma*pf[1], x0.z + gamma*pf[2], x0.w + gamma*pf[3],
                   x1.x + gamma*pf[4], x1.y + gamma*pf[5], x1.z + gamma*pf[6], x1.w + gamma*pf[7]};
    float4 w0 = {xn[0],xn[1],xn[2],xn[3]}, w1 = {xn[4],xn[5],xn[6],xn[7]};
    ((float4*)(g_X+bidx))[lane] = w0; ((float4*)(g_X+bidx))[lane+32] = w1;
    float s = 0.f;
    #pragma unroll
    for (int j = 0; j < 8; j++) s += xn[j];
    float m = warpSum(s) * (1.f/CC);
    float vs = 0.f;
    #pragma unroll
    for (int j = 0; j < 8; j++) { xn[j] -= m; vs += xn[j]*xn[j]; }
    float r = rsqrtf(warpSum(vs) * (1.f/CC) + EPSI);
    float4 ga = ((const float4*)n3g)[lane], gb = ((const float4*)n3g)[lane+32];
    float4 ba = ((const float4*)n3b)[lane], bb = ((const float4*)n3b)[lane+32];
    float gf[8] = {ga.x,ga.y,ga.z,ga.w,gb.x,gb.y,gb.z,gb.w};
    float bf_[8] = {ba.x,ba.y,ba.z,ba.w,bb.x,bb.y,bb.z,bb.w};
    float o[8];
    #pragma unroll
    for (int j = 0; j < 8; j++) o[j] = xn[j]*r*gf[j] + bf_[j];
    uint2* Ob2 = (uint2*)(g_XAb + bidx);
    uint2 q0; q0.x = packbf(o[0],o[1]); q0.y = packbf(o[2],o[3]);
    uint2 q1; q1.x = packbf(o[4],o[5]); q1.y = packbf(o[6],o[7]);
    Ob2[lane] = q0; Ob2[lane+32] = q1;
}

// ---------------- K12: temporal downsample ----------------
__global__ void k_down(float* __restrict__ out) {
    int i = blockIdx.x * blockDim.x + threadIdx.x;
    const float4* X4 = (const float4*)g_X;
    const int EC4 = EE*CC/4;
    int ec = i % EC4;
    int rest = i / EC4;
    int t2 = rest % 48;
    int b  = rest / 48;
    int in0 = (b*96 + 2*t2) * EC4 + ec;
    float4 a = X4[in0], c = X4[in0 + EC4];
    float4 o;
    o.x = 0.5f*(a.x + c.x); o.y = 0.5f*(a.y + c.y);
    o.z = 0.5f*(a.z + c.z); o.w = 0.5f*(a.w + c.w);
    ((float4*)out)[i] = o;
}

// ---------------- host ----------------
extern "C" void kernel_launch(void* const* d_in, const int* in_sizes, int n_in,
                              void* d_out, int out_size) {
    const float* x    = (const float*)d_in[0];
    const float* adj  = (const float*)d_in[1];
    const float* n1g  = (const float*)d_in[2];
    const float* n1b  = (const float*)d_in[3];
    const float* swq  = (const float*)d_in[4];
    const float* swk  = (const float*)d_in[5];
    const float* swv  = (const float*)d_in[6];
    const float* swp  = (const float*)d_in[7];
    const float* sbp  = (const float*)d_in[8];
    const float* sng  = (const float*)d_in[9];
    const float* snb  = (const float*)d_in[10];
    const float* sgam = (const float*)d_in[11];
    const float* n2g  = (const float*)d_in[12];
    const float* n2b  = (const float*)d_in[13];
    const float* twq  = (const float*)d_in[14];
    const float* twk  = (const float*)d_in[15];
    const float* twv  = (const float*)d_in[16];
    const float* twp  = (const float*)d_in[17];
    const float* tbp  = (const float*)d_in[18];
    const float* tgam = (const float*)d_in[19];
    const float* n3g  = (const float*)d_in[20];
    const float* n3b  = (const float*)d_in[21];
    const float* mw1  = (const float*)d_in[22];
    const float* mb1  = (const float*)d_in[23];
    const float* mw2  = (const float*)d_in[24];
    const float* mb2  = (const float*)d_in[25];

    float *X;
    __nv_bfloat16 *XAb, *QKVb, *Ob, *Pb, *Hb, *WB;
    cudaGetSymbolAddress((void**)&X,    g_X);
    cudaGetSymbolAddress((void**)&XAb,  g_XAb);
    cudaGetSymbolAddress((void**)&QKVb, g_QKVb);
    cudaGetSymbolAddress((void**)&Ob,   g_Ob);
    cudaGetSymbolAddress((void**)&Pb,   g_Pb);
    cudaGetSymbolAddress((void**)&Hb,   g_Hb);
    cudaGetSymbolAddress((void**)&WB,   g_WB);

    cudaFuncSetAttribute(attn_mma<false>, cudaFuncAttributeMaxDynamicSharedMemorySize, ATTN_SMEM);
    cudaFuncSetAttribute(attn_mma<true>,  cudaFuncAttributeMaxDynamicSharedMemorySize, ATTN_SMEM);

    dim3 g256(2, NROWS/128);     // N=256
    dim3 g768(6, NROWS/128);     // N=768 fused QKV
    dim3 g1024(8, NROWS/128);    // N=1024

    k_wconv<<<2048, 256>>>(swq, swk, swv, swp, twq, twk, twv, twp, mw1, mw2);

    // ---- spatial block ----
    k_ln1<<<NROWS/8, 256>>>(x, n1g, n1b);
    hgemm_k<0,1><<<g768, 256>>>(XAb, WB+W_SQ, nullptr, nullptr, QKVb, NROWS, 768, CC);
    attn_mma<false><<<dim3(BB*TT, HH), 256, ATTN_SMEM>>>(QKVb, Ob, adj);
    hgemm_k<1,1><<<g256, 256>>>(Ob, WB+W_SP, sbp, nullptr, Pb, NROWS, CC, CC);
    k_fuse1<<<NROWS/8, 256>>>(sng, snb, sgam, n2g, n2b);

    // ---- temporal block ----
    hgemm_k<0,1><<<g768, 256>>>(XAb, WB+W_TQ, nullptr, nullptr, QKVb, NROWS, 768, CC);
    attn_mma<true><<<dim3(BB*EE, HH), 256, ATTN_SMEM>>>(QKVb, Ob, nullptr);
    hgemm_k<1,1><<<g256, 256>>>(Ob, WB+W_TP, tbp, nullptr, Pb, NROWS, CC, CC);
    k_fuse2<<<NROWS/8, 256>>>(tgam, n3g, n3b);

    // ---- MLP ----
    hgemm_k<2,1><<<g1024, 256>>>(XAb, WB+W_M1, mb1, nullptr, Hb, NROWS, HIDN, CC);
    hgemm_k<3,0><<<g256, 256>>>(Hb, WB+W_M2, mb2, X, X, NROWS, CC, HIDN);

    // ---- downsample ----
    k_down<<<(BB*48*EE*CC/4)/256, 256>>>((float*)d_out);

    (void)in_sizes; (void)n_in; (void)out_size;
}